// round 12
// baseline (speedup 1.0000x reference)
#include <cuda_runtime.h>
#include <cuda_fp16.h>
#include <cstdint>

// Problem constants
#define NNODES  50000
#define CDIM    128
#define MDIM    9
#define CHUNK   32
#define NCHUNKS ((NNODES + CHUNK - 1) / CHUNK)      // 1563
#define G_FUSED 74                                  // 74*2 = 148 CTAs (1/SM)
#define GRP_F   64                                  // final: 64*9 = 576 CTAs (4/SM)
#define PITCH   136                                 // fp16 pitch; 272B rows
#define WIMG_B  (128 * PITCH * 2)                   // 34816 B full 128x128 fp16 W image
#define WSL_B   (64 * PITCH * 2)                    // 17408 B 64-row W slice
#define AIMG_B  (CHUNK * PITCH * 2)                 // 8704 B 32x128 fp16 A image
#define STG_B   (CHUNK * CDIM * 4)                  // 16384 B fp32 A stage
#define XP      72                                  // xl/xr smem pitch (halves)
#define XLS_B   (MDIM * CHUNK * XP * 2)             // 41472 B per tensor

// ---------------------------------------------------------------------------
// Device scratch
// ---------------------------------------------------------------------------
__device__ float g_w3j[128];
__device__ __align__(16) char g_wimg[9 * WIMG_B];
__device__ __half g_xl[(size_t)NNODES * MDIM * CDIM];   // TP output (fp16)

// ---------------------------------------------------------------------------
// HMMA + ldmatrix + cp.async helpers
// ---------------------------------------------------------------------------
__device__ __forceinline__ void mma_f16(float* d, const uint32_t* a, uint32_t b0, uint32_t b1) {
    asm volatile(
        "mma.sync.aligned.m16n8k16.row.col.f32.f16.f16.f32 "
        "{%0,%1,%2,%3}, {%4,%5,%6,%7}, {%8,%9}, {%0,%1,%2,%3};"
        : "+f"(d[0]), "+f"(d[1]), "+f"(d[2]), "+f"(d[3])
        : "r"(a[0]), "r"(a[1]), "r"(a[2]), "r"(a[3]), "r"(b0), "r"(b1));
}
__device__ __forceinline__ void ldsm_x4(uint32_t& r0, uint32_t& r1, uint32_t& r2, uint32_t& r3,
                                        uint32_t addr) {
    asm volatile("ldmatrix.sync.aligned.m8n8.x4.shared.b16 {%0,%1,%2,%3}, [%4];"
                 : "=r"(r0), "=r"(r1), "=r"(r2), "=r"(r3) : "r"(addr));
}
__device__ __forceinline__ uint32_t smem_u32(const void* p) {
    return (uint32_t)__cvta_generic_to_shared(p);
}
__device__ __forceinline__ void cp_async16(uint32_t dst, const void* src, bool valid) {
    int sz = valid ? 16 : 0;
    asm volatile("cp.async.cg.shared.global [%0], [%1], 16, %2;"
                 :: "r"(dst), "l"(src), "r"(sz));
}
__device__ __forceinline__ void cp_commit() { asm volatile("cp.async.commit_group;"); }
__device__ __forceinline__ void cp_wait0()  { asm volatile("cp.async.wait_group 0;" ::: "memory"); }
__device__ __forceinline__ void cp_wait1()  { asm volatile("cp.async.wait_group 1;" ::: "memory"); }

// ---------------------------------------------------------------------------
// Wigner-3j init — parallel (3 blocks x 128 threads)
// ---------------------------------------------------------------------------
struct C2 { double r, i; };
__device__ __forceinline__ C2 cmul(C2 a, C2 b) { return { a.r*b.r - a.i*b.i, a.r*b.i + a.i*b.r }; }
__device__ double dfact(int n) { double r = 1.0; for (int i = 2; i <= n; ++i) r *= (double)i; return r; }

__device__ double su2cg(int j1, int m1, int j2, int m2, int j3, int m3) {
    if (m3 != m1 + m2) return 0.0;
    int vmin = -j1 + j2 + m3; if (-j1 + m1 > vmin) vmin = -j1 + m1; if (0 > vmin) vmin = 0;
    int vmax = j2 + j3 + m1; if (j3 - j1 + j2 < vmax) vmax = j3 - j1 + j2; if (j3 + m3 < vmax) vmax = j3 + m3;
    double pref = sqrt((double)(2*j3+1) * dfact(j3+j1-j2) * dfact(j3-j1+j2) * dfact(j1+j2-j3)
                       / dfact(j1+j2+j3+1)
                       * dfact(j3+m3) * dfact(j3-m3)
                       / (dfact(j1-m1) * dfact(j1+m1) * dfact(j2-m2) * dfact(j2+m2)));
    double s = 0.0;
    for (int v = vmin; v <= vmax; ++v) {
        double sign = ((v + j2 + m2) & 1) ? -1.0 : 1.0;
        s += sign / dfact(v) * dfact(j2+j3+m1-v) * dfact(j1-m1+v)
             / (dfact(j3-j1+j2-v) * dfact(j3+m3-v) * dfact(v+j1-j2-m3));
    }
    return pref * s;
}

__device__ void qmat(int l, C2 Q[5][5]) {
    for (int a = 0; a < 5; ++a) for (int b = 0; b < 5; ++b) Q[a][b] = {0.0, 0.0};
    const double is2 = 0.7071067811865475244;
    for (int m = -l; m < 0; ++m) {
        Q[l+m][l-m] = { is2, 0.0 };
        Q[l+m][l+m] = { 0.0, -is2 };
    }
    Q[l][l] = { 1.0, 0.0 };
    for (int m = 1; m <= l; ++m) {
        double s = (m & 1) ? -1.0 : 1.0;
        Q[l+m][l+m] = { s * is2, 0.0 };
        Q[l+m][l-m] = { 0.0, s * is2 };
    }
    C2 f = (l == 0) ? C2{1.0, 0.0} : (l == 1) ? C2{0.0, -1.0} : C2{-1.0, 0.0};
    for (int a = 0; a < 2*l+1; ++a) for (int b = 0; b < 2*l+1; ++b) Q[a][b] = cmul(Q[a][b], f);
}

__global__ void w3j_init_kernel() {
    __shared__ double cgs[125];
    __shared__ double crs[125];
    __shared__ double red[128];

    const int tid = threadIdx.x;
    const int blk = blockIdx.x;
    const int l1 = (blk == 0) ? 2 : 1;
    const int l2 = (blk == 2) ? 1 : 2;
    const int lo = blk == 0 ? 0 : (blk == 1 ? 1 : 2);
    const double alpha = (blk == 0) ? 1.0 : (blk == 1 ? 1.7320508075688772935 : 2.2360679774997896964);
    const int off = (blk == 0) ? 0 : (blk == 1 ? 25 : 70);
    const int d1 = 2*l1+1, d2 = 2*l2+1, d3 = 2*lo+1;
    const int nel = d1 * d2 * d3;

    if (tid < nel) {
        int i = tid / (d2 * d3), k = (tid / d3) % d2, n = tid % d3;
        cgs[tid] = su2cg(l1, i - l1, l2, k - l2, lo, n - lo);
    }
    __syncthreads();

    double cr = 0.0;
    if (tid < nel) {
        C2 Q1[5][5], Q2[5][5], Q3[5][5];
        qmat(l1, Q1); qmat(l2, Q2); qmat(lo, Q3);
        int a = tid / (d2 * d3), b = (tid / d3) % d2, c = tid % d3;
        C2 s = {0.0, 0.0};
        for (int i = 0; i < d1; ++i)
            for (int k = 0; k < d2; ++k) {
                C2 q12 = cmul(Q1[i][a], Q2[k][b]);
                for (int n = 0; n < d3; ++n) {
                    double cg = cgs[(i * d2 + k) * d3 + n];
                    if (cg == 0.0) continue;
                    C2 q3c = { Q3[n][c].r, -Q3[n][c].i };
                    C2 t = cmul(q12, q3c);
                    s.r += t.r * cg; s.i += t.i * cg;
                }
            }
        cr = s.r;
        crs[tid] = cr;
    }

    red[tid] = (tid < nel) ? cr * cr : 0.0;
    __syncthreads();
    for (int stride = 64; stride > 0; stride >>= 1) {
        if (tid < stride) red[tid] += red[tid + stride];
        __syncthreads();
    }
    double inv = alpha * rsqrt(red[0]);

    if (tid < nel) g_w3j[off + tid] = (float)(crs[tid] * inv);
    if (blk == 2 && tid >= 115 && tid < 128) g_w3j[tid] = 0.0f;
}

// ---------------------------------------------------------------------------
// Weight prep: round fp32 W to fp16 image [cout][k], pitch PITCH.
// ---------------------------------------------------------------------------
__global__ void wsplit_kernel(const float* __restrict__ Wl,
                              const float* __restrict__ Wr,
                              const float* __restrict__ Wf) {
    int b = blockIdx.x;
    int which = b / 3, ll = b % 3;
    const float* W = (which == 0 ? Wl : which == 1 ? Wr : Wf) + ll * CDIM * CDIM;
    char* img = g_wimg + (size_t)b * WIMG_B;
    for (int i = threadIdx.x; i < CDIM * CDIM; i += blockDim.x) {
        int cout = i >> 7, k = i & 127;
        *(__half*)(img + (cout * PITCH + k) * 2) = __float2half_rn(W[i]);
    }
}

// ---------------------------------------------------------------------------
// FUSED LR + TP persistent kernel. grid = (G_FUSED, 2 channel-halves), 1 CTA/SM.
// Per chunk (32 nodes): for m=0..8 compute xl,xr (64 couts) into smem, then TP
// in-CTA and write fp16 result to g_xl.
// smem: Wsl[6] | img0|img1 | stage | xl_s | xr_s | w3s
// ---------------------------------------------------------------------------
__global__ __launch_bounds__(256, 1)
void fused_lr_tp_kernel(const float* __restrict__ src,
                        const float* __restrict__ bias0,
                        const float* __restrict__ bias1,
                        __half* __restrict__ tp_out)
{
    extern __shared__ __align__(16) char smem[];
    char* Wsl   = smem;                               // 6 * WSL_B
    char* img[2] = { smem + 6 * WSL_B, smem + 6 * WSL_B + AIMG_B };
    char* stg   = smem + 6 * WSL_B + 2 * AIMG_B;      // STG_B
    char* xl_s  = stg + STG_B;                        // XLS_B
    char* xr_s  = xl_s + XLS_B;                       // XLS_B
    float* w3s  = (float*)(xr_s + XLS_B);             // 128 floats

    const int tid = threadIdx.x, wid = tid >> 5, lane = tid & 31;
    const int g = lane >> 2, t = lane & 3;
    const int ch0 = blockIdx.y * 64;
    const int warpR = wid & 1, warpC = wid >> 1;      // 2 x 4 warps: 16 rows x 16 couts

    // prologue cp.async for first chunk, m=0 (start DRAM early)
    auto issue_a = [&](int c, int m) {
        int n0 = c * CHUNK;
        #pragma unroll
        for (int it = 0; it < 4; ++it) {
            int idx = it * 256 + tid;                 // 1024 16B lines
            int row = idx >> 5, c4 = (idx & 31) << 2;
            int n = n0 + row;
            cp_async16(smem_u32(stg) + (uint32_t)idx * 16,
                       &src[((size_t)n * MDIM + m) * CDIM + c4],
                       n < NNODES);
        }
        cp_commit();
    };

    int c = blockIdx.x;
    if (c < NCHUNKS) issue_a(c, 0);

    // stage W slices (rows ch0..ch0+63 of left/right images) + w3j
    #pragma unroll
    for (int b = 0; b < 6; ++b) {
        const float4* s = (const float4*)(g_wimg + (size_t)b * WIMG_B + (size_t)ch0 * PITCH * 2);
        float4* d = (float4*)(Wsl + b * WSL_B);
        for (int i = tid; i < WSL_B / 16; i += 256) d[i] = s[i];
    }
    if (tid < 128) w3s[tid] = g_w3j[tid];

    // per-lane ldmatrix offsets
    const int jm = lane >> 3, rr = lane & 7;
    const uint32_t aoff = (uint32_t)(((warpR * 16 + ((jm & 1) << 3) + rr) * PITCH
                                      + ((jm >> 1) << 3)) * 2);
    const uint32_t boff = (uint32_t)(((warpC * 16 + ((jm >> 1) << 3) + rr) * PITCH
                                      + ((jm & 1) << 3)) * 2);
    const uint32_t uWsl = smem_u32(Wsl);
    const uint32_t uImg[2] = { smem_u32(img[0]), smem_u32(img[1]) };

    for (; c < NCHUNKS; c += G_FUSED) {
        const int n0 = c * CHUNK;

        for (int m = 0; m < MDIM; ++m) {
            const int l = (m >= 4) ? 2 : (m >= 1) ? 1 : 0;
            cp_wait0();
            __syncthreads();                          // stage(m) landed; prev users done

            // convert fp32 stage -> fp16 image
            #pragma unroll
            for (int it = 0; it < 4; ++it) {
                int idx = it * 256 + tid;
                int row = idx >> 5, c4 = (idx & 31) << 2;
                float4 v = *(float4*)(stg + idx * 16);
                __half2 h01 = __floats2half2_rn(v.x, v.y);
                __half2 h23 = __floats2half2_rn(v.z, v.w);
                *(uint2*)(img[m & 1] + (row * PITCH + c4) * 2) =
                    make_uint2(*(uint32_t*)&h01, *(uint32_t*)&h23);
            }
            __syncthreads();                          // image ready; stage free

            if (m < 8) issue_a(c, m + 1);
            else if (c + G_FUSED < NCHUNKS) issue_a(c + G_FUSED, 0);

            // GEMM: 32 nodes x 64 couts x K=128, two outputs (L, R)
            const uint32_t uA = uImg[m & 1];
            float acc[2][2][4];
            #pragma unroll
            for (int o = 0; o < 2; ++o)
                #pragma unroll
                for (int cf = 0; cf < 2; ++cf)
                    #pragma unroll
                    for (int q = 0; q < 4; ++q) acc[o][cf][q] = 0.f;

            #pragma unroll
            for (int ks = 0; ks < 8; ++ks) {
                const uint32_t kofs = (uint32_t)(ks * 32);
                uint32_t a[4];
                ldsm_x4(a[0], a[1], a[2], a[3], uA + aoff + kofs);
                #pragma unroll
                for (int o = 0; o < 2; ++o) {
                    const uint32_t uWp = uWsl + (uint32_t)((o * 3 + l) * WSL_B);
                    uint32_t b0, b1, b2, b3;
                    ldsm_x4(b0, b1, b2, b3, uWp + boff + kofs);
                    mma_f16(acc[o][0], a, b0, b1);
                    mma_f16(acc[o][1], a, b2, b3);
                }
            }

            // epilogue: bias (m==0) + fp16 store into xl_s/xr_s
            #pragma unroll
            for (int o = 0; o < 2; ++o) {
                const float* bias = o ? bias1 : bias0;
                char* xs = o ? xr_s : xl_s;
                int r0 = warpR * 16 + g;
                #pragma unroll
                for (int cf = 0; cf < 2; ++cf) {
                    int cb = warpC * 16 + cf * 8 + 2 * t;
                    float bx = 0.f, by = 0.f;
                    if (m == 0) { bx = bias[ch0 + cb]; by = bias[ch0 + cb + 1]; }
                    __half2 h0 = __floats2half2_rn(acc[o][cf][0] + bx, acc[o][cf][1] + by);
                    __half2 h1 = __floats2half2_rn(acc[o][cf][2] + bx, acc[o][cf][3] + by);
                    *(__half2*)(xs + ((m * CHUNK + r0) * XP + cb) * 2) = h0;
                    *(__half2*)(xs + ((m * CHUNK + r0 + 8) * XP + cb) * 2) = h1;
                }
            }
        }
        __syncthreads();                              // all xl_s/xr_s written

        // --- TP in-CTA: 32 nodes x 32 half2-channels ---
        const __half2* XL = (const __half2*)xl_s;
        const __half2* XR = (const __half2*)xr_s;
        #pragma unroll
        for (int it = 0; it < 4; ++it) {
            int p = it * 256 + tid;
            int n = p >> 5, c2 = p & 31;
            int node = n0 + n;
            if (node >= NNODES) continue;

            float2 a1[3], b1[3], a2[5], b2[5];
            #pragma unroll
            for (int i = 0; i < 3; ++i) {
                a1[i] = __half22float2(XL[((1 + i) * CHUNK + n) * (XP / 2) + c2]);
                b1[i] = __half22float2(XR[((1 + i) * CHUNK + n) * (XP / 2) + c2]);
            }
            #pragma unroll
            for (int i = 0; i < 5; ++i) {
                a2[i] = __half22float2(XL[((4 + i) * CHUNK + n) * (XP / 2) + c2]);
                b2[i] = __half22float2(XR[((4 + i) * CHUNK + n) * (XP / 2) + c2]);
            }

            float2 o0 = make_float2(0.f, 0.f);
            #pragma unroll
            for (int i = 0; i < 5; ++i)
                #pragma unroll
                for (int j = 0; j < 5; ++j) {
                    float w = w3s[i * 5 + j];
                    o0.x += w * a2[i].x * b2[j].x;
                    o0.y += w * a2[i].y * b2[j].y;
                }

            float2 o1[3] = { {0.f,0.f}, {0.f,0.f}, {0.f,0.f} };
            #pragma unroll
            for (int i = 0; i < 3; ++i)
                #pragma unroll
                for (int j = 0; j < 5; ++j) {
                    float abx = a1[i].x * b2[j].x;
                    float aby = a1[i].y * b2[j].y;
                    #pragma unroll
                    for (int k = 0; k < 3; ++k) {
                        float w = w3s[25 + (i * 5 + j) * 3 + k];
                        o1[k].x += w * abx;
                        o1[k].y += w * aby;
                    }
                }

            float2 o2[5] = { {0.f,0.f}, {0.f,0.f}, {0.f,0.f}, {0.f,0.f}, {0.f,0.f} };
            #pragma unroll
            for (int i = 0; i < 3; ++i)
                #pragma unroll
                for (int j = 0; j < 3; ++j) {
                    float abx = a1[i].x * b1[j].x;
                    float aby = a1[i].y * b1[j].y;
                    #pragma unroll
                    for (int k = 0; k < 5; ++k) {
                        float w = w3s[70 + (i * 3 + j) * 5 + k];
                        o2[k].x += w * abx;
                        o2[k].y += w * aby;
                    }
                }

            __half2* OUT = (__half2*)&tp_out[((size_t)node * MDIM) * CDIM + ch0 + 2 * c2];
            OUT[0] = __floats2half2_rn(o0.x, o0.y);
            #pragma unroll
            for (int k = 0; k < 3; ++k) OUT[(1 + k) * (CDIM / 2)] = __floats2half2_rn(o1[k].x, o1[k].y);
            #pragma unroll
            for (int k = 0; k < 5; ++k) OUT[(4 + k) * (CDIM / 2)] = __floats2half2_rn(o2[k].x, o2[k].y);
        }
        // next chunk's first cp_wait0+__syncthreads orders TP reads vs new epilogue writes
    }
}

// ---------------------------------------------------------------------------
// Final GEMM: fp16 in (direct cp.async, double-buffered), fp32 out. 4 CTAs/SM.
// ---------------------------------------------------------------------------
__global__ __launch_bounds__(256, 4)
void f_gemm_kernel(const __half* __restrict__ src,
                   const float* __restrict__ bias0,
                   float* __restrict__ out0)
{
    extern __shared__ __align__(16) char smem[];
    char* Wsm  = smem;
    char* Aimg[2] = { smem + WIMG_B, smem + WIMG_B + AIMG_B };

    const int tid = threadIdx.x, wid = tid >> 5, lane = tid & 31;
    const int g = lane >> 2, t = lane & 3;
    const int m = blockIdx.y;
    const int l = (m >= 4) ? 2 : (m >= 1) ? 1 : 0;
    const int warpR = wid & 1, warpC = wid >> 1;

    {
        const float4* s0 = (const float4*)(g_wimg + (size_t)(6 + l) * WIMG_B);
        float4* d0 = (float4*)Wsm;
        for (int i = tid; i < WIMG_B / 16; i += 256) d0[i] = s0[i];
    }

    const int jm = lane >> 3, rr = lane & 7;
    const uint32_t aoff = (uint32_t)(((warpR * 16 + ((jm & 1) << 3) + rr) * PITCH
                                      + ((jm >> 1) << 3)) * 2);
    uint32_t boff[2];
    #pragma unroll
    for (int cp = 0; cp < 2; ++cp) {
        int n = warpC * 32 + cp * 16 + ((jm >> 1) << 3) + rr;
        boff[cp] = (uint32_t)((n * PITCH + ((jm & 1) << 3)) * 2);
    }
    const uint32_t uW = smem_u32(Wsm);
    const uint32_t uAimg[2] = { smem_u32(Aimg[0]), smem_u32(Aimg[1]) };

    auto issue_chunk = [&](int c, int buf) {
        int n0 = c * CHUNK;
        #pragma unroll
        for (int it = 0; it < 2; ++it) {
            int idx = it * 256 + tid;              // 512 16B lines
            int row = idx >> 4, c8 = (idx & 15) << 3;
            int n = n0 + row;
            cp_async16(uAimg[buf] + (uint32_t)(row * PITCH + c8) * 2,
                       &src[((size_t)n * MDIM + m) * CDIM + c8],
                       n < NNODES);
        }
        cp_commit();
    };

    int c = blockIdx.x;
    int buf = 0;
    if (c < NCHUNKS) issue_chunk(c, 0);

    for (; c < NCHUNKS; c += GRP_F) {
        const int n0 = c * CHUNK;
        bool more = (c + GRP_F < NCHUNKS);
        if (more) issue_chunk(c + GRP_F, buf ^ 1);
        if (more) cp_wait1(); else cp_wait0();
        __syncthreads();

        const uint32_t uA = uAimg[buf];
        float acc[4][4];
        #pragma unroll
        for (int cf = 0; cf < 4; ++cf)
            #pragma unroll
            for (int q = 0; q < 4; ++q) acc[cf][q] = 0.f;

        #pragma unroll
        for (int ks = 0; ks < 8; ++ks) {
            const uint32_t kofs = (uint32_t)(ks * 32);
            uint32_t a[4];
            ldsm_x4(a[0], a[1], a[2], a[3], uA + aoff + kofs);
            #pragma unroll
            for (int cp = 0; cp < 2; ++cp) {
                uint32_t b0, b1, b2, b3;
                ldsm_x4(b0, b1, b2, b3, uW + boff[cp] + kofs);
                mma_f16(acc[2*cp],     a, b0, b1);
                mma_f16(acc[2*cp + 1], a, b2, b3);
            }
        }

        {
            int r0 = n0 + warpR * 16 + g;
            int r1 = r0 + 8;
            #pragma unroll
            for (int cf = 0; cf < 4; ++cf) {
                int cb = warpC * 32 + cf * 8 + 2 * t;
                float bx = 0.f, by = 0.f;
                if (m == 0) { bx = bias0[cb]; by = bias0[cb + 1]; }
                if (r0 < NNODES)
                    *(float2*)&out0[((size_t)r0 * MDIM + m) * CDIM + cb] =
                        make_float2(acc[cf][0] + bx, acc[cf][1] + by);
                if (r1 < NNODES)
                    *(float2*)&out0[((size_t)r1 * MDIM + m) * CDIM + cb] =
                        make_float2(acc[cf][2] + bx, acc[cf][3] + by);
            }
        }
        __syncthreads();
        buf ^= 1;
    }
}

// ---------------------------------------------------------------------------
extern "C" void kernel_launch(void* const* d_in, const int* in_sizes, int n_in,
                              void* d_out, int out_size) {
    const float* x  = (const float*)d_in[0];
    const float* Wl = (const float*)d_in[1];
    const float* bl = (const float*)d_in[2];
    const float* Wr = (const float*)d_in[3];
    const float* br = (const float*)d_in[4];
    const float* Wf = (const float*)d_in[5];
    const float* bf = (const float*)d_in[6];
    float* out = (float*)d_out;

    __half* pxl = nullptr;
    cudaGetSymbolAddress((void**)&pxl, g_xl);

    const int FUSED_SMEM = 6 * WSL_B + 2 * AIMG_B + STG_B + 2 * XLS_B + 512;  // 221696
    const int F_SMEM     = WIMG_B + 2 * AIMG_B;                               // 52224
    cudaFuncSetAttribute(fused_lr_tp_kernel,
                         cudaFuncAttributeMaxDynamicSharedMemorySize, FUSED_SMEM);
    cudaFuncSetAttribute(f_gemm_kernel,
                         cudaFuncAttributeMaxDynamicSharedMemorySize, F_SMEM);

    w3j_init_kernel<<<3, 128>>>();
    wsplit_kernel<<<9, 256>>>(Wl, Wr, Wf);

    // fused left+right linears + CG tensor product -> fp16 g_xl
    fused_lr_tp_kernel<<<dim3(G_FUSED, 2), 256, FUSED_SMEM>>>(x, bl, br, pxl);
    // final linear -> fp32 d_out
    f_gemm_kernel<<<dim3(GRP_F, MDIM), 256, F_SMEM>>>(pxl, bf, out);
}

// round 13
// speedup vs baseline: 1.1116x; 1.1116x over previous
#include <cuda_runtime.h>
#include <cuda_fp16.h>
#include <cstdint>

// Problem constants
#define NNODES  50000
#define CDIM    128
#define MDIM    9
#define CHUNK   32
#define NCHUNKS ((NNODES + CHUNK - 1) / CHUNK)      // 1563
#define GRP_LR  32                                  // 32*8 = 256 CTAs (2/SM)
#define GRP_F   64                                  // 64*9 = 576 CTAs (4/SM)
#define PITCH   136                                 // fp16 pitch; 272B rows
#define WIMG_B  (128 * PITCH * 2)                   // 34816 B per 128x128 fp16 W image
#define AIMG_B  (CHUNK * PITCH * 2)                 // 8704 B per 32x128 fp16 A image
#define STG_B   (CHUNK * CDIM * 4)                  // 16384 B fp32 A stage (LR only)

// ---------------------------------------------------------------------------
// Device scratch (fp16 intermediates)
// ---------------------------------------------------------------------------
__device__ float g_w3j[128];
__device__ __align__(16) char g_wimg[9 * WIMG_B];
__device__ __half g_xl[(size_t)NNODES * MDIM * CDIM];
__device__ __half g_xr[(size_t)NNODES * MDIM * CDIM];

// ---------------------------------------------------------------------------
// HMMA + ldmatrix + cp.async helpers
// ---------------------------------------------------------------------------
__device__ __forceinline__ void mma_f16(float* d, const uint32_t* a, uint32_t b0, uint32_t b1) {
    asm volatile(
        "mma.sync.aligned.m16n8k16.row.col.f32.f16.f16.f32 "
        "{%0,%1,%2,%3}, {%4,%5,%6,%7}, {%8,%9}, {%0,%1,%2,%3};"
        : "+f"(d[0]), "+f"(d[1]), "+f"(d[2]), "+f"(d[3])
        : "r"(a[0]), "r"(a[1]), "r"(a[2]), "r"(a[3]), "r"(b0), "r"(b1));
}
__device__ __forceinline__ void ldsm_x4(uint32_t& r0, uint32_t& r1, uint32_t& r2, uint32_t& r3,
                                        uint32_t addr) {
    asm volatile("ldmatrix.sync.aligned.m8n8.x4.shared.b16 {%0,%1,%2,%3}, [%4];"
                 : "=r"(r0), "=r"(r1), "=r"(r2), "=r"(r3) : "r"(addr));
}
__device__ __forceinline__ uint32_t smem_u32(const void* p) {
    return (uint32_t)__cvta_generic_to_shared(p);
}
__device__ __forceinline__ void cp_async16(uint32_t dst, const void* src, bool valid) {
    int sz = valid ? 16 : 0;
    asm volatile("cp.async.cg.shared.global [%0], [%1], 16, %2;"
                 :: "r"(dst), "l"(src), "r"(sz));
}
__device__ __forceinline__ void cp_commit() { asm volatile("cp.async.commit_group;"); }
__device__ __forceinline__ void cp_wait0()  { asm volatile("cp.async.wait_group 0;" ::: "memory"); }
__device__ __forceinline__ void cp_wait1()  { asm volatile("cp.async.wait_group 1;" ::: "memory"); }

// ---------------------------------------------------------------------------
// Wigner-3j init — parallel (3 blocks x 128 threads)
// ---------------------------------------------------------------------------
struct C2 { double r, i; };
__device__ __forceinline__ C2 cmul(C2 a, C2 b) { return { a.r*b.r - a.i*b.i, a.r*b.i + a.i*b.r }; }
__device__ double dfact(int n) { double r = 1.0; for (int i = 2; i <= n; ++i) r *= (double)i; return r; }

__device__ double su2cg(int j1, int m1, int j2, int m2, int j3, int m3) {
    if (m3 != m1 + m2) return 0.0;
    int vmin = -j1 + j2 + m3; if (-j1 + m1 > vmin) vmin = -j1 + m1; if (0 > vmin) vmin = 0;
    int vmax = j2 + j3 + m1; if (j3 - j1 + j2 < vmax) vmax = j3 - j1 + j2; if (j3 + m3 < vmax) vmax = j3 + m3;
    double pref = sqrt((double)(2*j3+1) * dfact(j3+j1-j2) * dfact(j3-j1+j2) * dfact(j1+j2-j3)
                       / dfact(j1+j2+j3+1)
                       * dfact(j3+m3) * dfact(j3-m3)
                       / (dfact(j1-m1) * dfact(j1+m1) * dfact(j2-m2) * dfact(j2+m2)));
    double s = 0.0;
    for (int v = vmin; v <= vmax; ++v) {
        double sign = ((v + j2 + m2) & 1) ? -1.0 : 1.0;
        s += sign / dfact(v) * dfact(j2+j3+m1-v) * dfact(j1-m1+v)
             / (dfact(j3-j1+j2-v) * dfact(j3+m3-v) * dfact(v+j1-j2-m3));
    }
    return pref * s;
}

__device__ void qmat(int l, C2 Q[5][5]) {
    for (int a = 0; a < 5; ++a) for (int b = 0; b < 5; ++b) Q[a][b] = {0.0, 0.0};
    const double is2 = 0.7071067811865475244;
    for (int m = -l; m < 0; ++m) {
        Q[l+m][l-m] = { is2, 0.0 };
        Q[l+m][l+m] = { 0.0, -is2 };
    }
    Q[l][l] = { 1.0, 0.0 };
    for (int m = 1; m <= l; ++m) {
        double s = (m & 1) ? -1.0 : 1.0;
        Q[l+m][l+m] = { s * is2, 0.0 };
        Q[l+m][l-m] = { 0.0, s * is2 };
    }
    C2 f = (l == 0) ? C2{1.0, 0.0} : (l == 1) ? C2{0.0, -1.0} : C2{-1.0, 0.0};
    for (int a = 0; a < 2*l+1; ++a) for (int b = 0; b < 2*l+1; ++b) Q[a][b] = cmul(Q[a][b], f);
}

__global__ void w3j_init_kernel() {
    __shared__ double cgs[125];
    __shared__ double crs[125];
    __shared__ double red[128];

    const int tid = threadIdx.x;
    const int blk = blockIdx.x;
    const int l1 = (blk == 0) ? 2 : 1;
    const int l2 = (blk == 2) ? 1 : 2;
    const int lo = blk == 0 ? 0 : (blk == 1 ? 1 : 2);
    const double alpha = (blk == 0) ? 1.0 : (blk == 1 ? 1.7320508075688772935 : 2.2360679774997896964);
    const int off = (blk == 0) ? 0 : (blk == 1 ? 25 : 70);
    const int d1 = 2*l1+1, d2 = 2*l2+1, d3 = 2*lo+1;
    const int nel = d1 * d2 * d3;

    if (tid < nel) {
        int i = tid / (d2 * d3), k = (tid / d3) % d2, n = tid % d3;
        cgs[tid] = su2cg(l1, i - l1, l2, k - l2, lo, n - lo);
    }
    __syncthreads();

    double cr = 0.0;
    if (tid < nel) {
        C2 Q1[5][5], Q2[5][5], Q3[5][5];
        qmat(l1, Q1); qmat(l2, Q2); qmat(lo, Q3);
        int a = tid / (d2 * d3), b = (tid / d3) % d2, c = tid % d3;
        C2 s = {0.0, 0.0};
        for (int i = 0; i < d1; ++i)
            for (int k = 0; k < d2; ++k) {
                C2 q12 = cmul(Q1[i][a], Q2[k][b]);
                for (int n = 0; n < d3; ++n) {
                    double cg = cgs[(i * d2 + k) * d3 + n];
                    if (cg == 0.0) continue;
                    C2 q3c = { Q3[n][c].r, -Q3[n][c].i };
                    C2 t = cmul(q12, q3c);
                    s.r += t.r * cg; s.i += t.i * cg;
                }
            }
        cr = s.r;
        crs[tid] = cr;
    }

    red[tid] = (tid < nel) ? cr * cr : 0.0;
    __syncthreads();
    for (int stride = 64; stride > 0; stride >>= 1) {
        if (tid < stride) red[tid] += red[tid + stride];
        __syncthreads();
    }
    double inv = alpha * rsqrt(red[0]);

    if (tid < nel) g_w3j[off + tid] = (float)(crs[tid] * inv);
    if (blk == 2 && tid >= 115 && tid < 128) g_w3j[tid] = 0.0f;
}

// ---------------------------------------------------------------------------
// Weight prep: round fp32 W to fp16 image [cout][k], pitch PITCH.
// ---------------------------------------------------------------------------
__global__ void wsplit_kernel(const float* __restrict__ Wl,
                              const float* __restrict__ Wr,
                              const float* __restrict__ Wf) {
    int b = blockIdx.x;
    int which = b / 3, ll = b % 3;
    const float* W = (which == 0 ? Wl : which == 1 ? Wr : Wf) + ll * CDIM * CDIM;
    char* img = g_wimg + (size_t)b * WIMG_B;
    for (int i = threadIdx.x; i < CDIM * CDIM; i += blockDim.x) {
        int cout = i >> 7, k = i & 127;
        *(__half*)(img + (cout * PITCH + k) * 2) = __float2half_rn(W[i]);
    }
}

// ---------------------------------------------------------------------------
// LR GEMM: fp32 in, 2 fp16 outputs. m = 1..8 ONLY (l=0 of xl/xr unused by TP;
// biases bl/br touch only l=0 and are therefore irrelevant). 2 CTAs/SM.
// ---------------------------------------------------------------------------
__global__ __launch_bounds__(256, 2)
void lr_gemm_kernel(const float* __restrict__ src,
                    __half* __restrict__ out0,
                    __half* __restrict__ out1)
{
    extern __shared__ __align__(16) char smem[];
    char* Wsm   = smem;
    char* A_img = smem + 2 * WIMG_B;
    char* stg   = A_img + AIMG_B;

    const int tid = threadIdx.x, wid = tid >> 5, lane = tid & 31;
    const int g = lane >> 2, t = lane & 3;
    const int m = blockIdx.y + 1;                  // m = 1..8
    const int l = (m >= 4) ? 2 : 1;
    const int warpR = wid & 1, warpC = wid >> 1;   // 2 x 4 warps

    // Stage W images once (left = wb 0+l, right = wb 3+l)
    {
        const float4* s0 = (const float4*)(g_wimg + (size_t)l * WIMG_B);
        const float4* s1 = (const float4*)(g_wimg + (size_t)(3 + l) * WIMG_B);
        float4* d0 = (float4*)Wsm;
        float4* d1 = (float4*)(Wsm + WIMG_B);
        for (int i = tid; i < WIMG_B / 16; i += 256) { d0[i] = s0[i]; d1[i] = s1[i]; }
    }

    const int jm = lane >> 3, rr = lane & 7;
    const uint32_t aoff = (uint32_t)(((warpR * 16 + ((jm & 1) << 3) + rr) * PITCH
                                      + ((jm >> 1) << 3)) * 2);
    uint32_t boff[2];
    #pragma unroll
    for (int cp = 0; cp < 2; ++cp) {
        int n = warpC * 32 + cp * 16 + ((jm >> 1) << 3) + rr;
        boff[cp] = (uint32_t)((n * PITCH + ((jm & 1) << 3)) * 2);
    }

    const uint32_t uA = smem_u32(A_img), uW = smem_u32(Wsm), uStg = smem_u32(stg);

    auto issue_chunk = [&](int c) {
        int n0 = c * CHUNK;
        #pragma unroll
        for (int it = 0; it < 4; ++it) {
            int idx = it * 256 + tid;
            int row = idx >> 5, c4 = (idx & 31) << 2;
            int n = n0 + row;
            cp_async16(uStg + (uint32_t)idx * 16,
                       &src[((size_t)n * MDIM + m) * CDIM + c4],
                       n < NNODES);
        }
        cp_commit();
    };

    int c = blockIdx.x;
    if (c < NCHUNKS) issue_chunk(c);

    for (; c < NCHUNKS; c += GRP_LR) {
        const int n0 = c * CHUNK;
        cp_wait0();
        __syncthreads();

        #pragma unroll
        for (int it = 0; it < 4; ++it) {
            int idx = it * 256 + tid;
            int row = idx >> 5, c4 = (idx & 31) << 2;
            float4 v = *(float4*)(stg + idx * 16);
            __half2 h01 = __floats2half2_rn(v.x, v.y);
            __half2 h23 = __floats2half2_rn(v.z, v.w);
            *(uint2*)(A_img + (row * PITCH + c4) * 2) =
                make_uint2(*(uint32_t*)&h01, *(uint32_t*)&h23);
        }
        __syncthreads();

        if (c + GRP_LR < NCHUNKS) issue_chunk(c + GRP_LR);

        float acc[2][4][4];
        #pragma unroll
        for (int o = 0; o < 2; ++o)
            #pragma unroll
            for (int cf = 0; cf < 4; ++cf)
                #pragma unroll
                for (int q = 0; q < 4; ++q) acc[o][cf][q] = 0.f;

        #pragma unroll
        for (int ks = 0; ks < 8; ++ks) {
            const uint32_t kofs = (uint32_t)(ks * 32);
            uint32_t a[4];
            ldsm_x4(a[0], a[1], a[2], a[3], uA + aoff + kofs);
            #pragma unroll
            for (int o = 0; o < 2; ++o) {
                const uint32_t uWp = uW + o * WIMG_B;
                #pragma unroll
                for (int cp = 0; cp < 2; ++cp) {
                    uint32_t b0, b1, b2, b3;
                    ldsm_x4(b0, b1, b2, b3, uWp + boff[cp] + kofs);
                    mma_f16(acc[o][2*cp],     a, b0, b1);
                    mma_f16(acc[o][2*cp + 1], a, b2, b3);
                }
            }
        }

        #pragma unroll
        for (int o = 0; o < 2; ++o) {
            __half* out = o ? out1 : out0;
            int r0 = n0 + warpR * 16 + g;
            int r1 = r0 + 8;
            #pragma unroll
            for (int cf = 0; cf < 4; ++cf) {
                int cb = warpC * 32 + cf * 8 + 2 * t;
                if (r0 < NNODES) {
                    __half2 h = __floats2half2_rn(acc[o][cf][0], acc[o][cf][1]);
                    *(uint32_t*)&out[((size_t)r0 * MDIM + m) * CDIM + cb] = *(uint32_t*)&h;
                }
                if (r1 < NNODES) {
                    __half2 h = __floats2half2_rn(acc[o][cf][2], acc[o][cf][3]);
                    *(uint32_t*)&out[((size_t)r1 * MDIM + m) * CDIM + cb] = *(uint32_t*)&h;
                }
            }
        }
    }
}

// ---------------------------------------------------------------------------
// Final GEMM: fp16 in (direct cp.async, double-buffered), fp32 out. 4 CTAs/SM.
// ---------------------------------------------------------------------------
__global__ __launch_bounds__(256, 4)
void f_gemm_kernel(const __half* __restrict__ src,
                   const float* __restrict__ bias0,
                   float* __restrict__ out0)
{
    extern __shared__ __align__(16) char smem[];
    char* Wsm  = smem;
    char* Aimg[2] = { smem + WIMG_B, smem + WIMG_B + AIMG_B };

    const int tid = threadIdx.x, wid = tid >> 5, lane = tid & 31;
    const int g = lane >> 2, t = lane & 3;
    const int m = blockIdx.y;
    const int l = (m >= 4) ? 2 : (m >= 1) ? 1 : 0;
    const int warpR = wid & 1, warpC = wid >> 1;

    {
        const float4* s0 = (const float4*)(g_wimg + (size_t)(6 + l) * WIMG_B);
        float4* d0 = (float4*)Wsm;
        for (int i = tid; i < WIMG_B / 16; i += 256) d0[i] = s0[i];
    }

    const int jm = lane >> 3, rr = lane & 7;
    const uint32_t aoff = (uint32_t)(((warpR * 16 + ((jm & 1) << 3) + rr) * PITCH
                                      + ((jm >> 1) << 3)) * 2);
    uint32_t boff[2];
    #pragma unroll
    for (int cp = 0; cp < 2; ++cp) {
        int n = warpC * 32 + cp * 16 + ((jm >> 1) << 3) + rr;
        boff[cp] = (uint32_t)((n * PITCH + ((jm & 1) << 3)) * 2);
    }
    const uint32_t uW = smem_u32(Wsm);
    const uint32_t uAimg[2] = { smem_u32(Aimg[0]), smem_u32(Aimg[1]) };

    auto issue_chunk = [&](int c, int buf) {
        int n0 = c * CHUNK;
        #pragma unroll
        for (int it = 0; it < 2; ++it) {
            int idx = it * 256 + tid;
            int row = idx >> 4, c8 = (idx & 15) << 3;
            int n = n0 + row;
            cp_async16(uAimg[buf] + (uint32_t)(row * PITCH + c8) * 2,
                       &src[((size_t)n * MDIM + m) * CDIM + c8],
                       n < NNODES);
        }
        cp_commit();
    };

    int c = blockIdx.x;
    int buf = 0;
    if (c < NCHUNKS) issue_chunk(c, 0);

    for (; c < NCHUNKS; c += GRP_F) {
        const int n0 = c * CHUNK;
        bool more = (c + GRP_F < NCHUNKS);
        if (more) issue_chunk(c + GRP_F, buf ^ 1);
        if (more) cp_wait1(); else cp_wait0();
        __syncthreads();

        const uint32_t uA = uAimg[buf];
        float acc[4][4];
        #pragma unroll
        for (int cf = 0; cf < 4; ++cf)
            #pragma unroll
            for (int q = 0; q < 4; ++q) acc[cf][q] = 0.f;

        #pragma unroll
        for (int ks = 0; ks < 8; ++ks) {
            const uint32_t kofs = (uint32_t)(ks * 32);
            uint32_t a[4];
            ldsm_x4(a[0], a[1], a[2], a[3], uA + aoff + kofs);
            #pragma unroll
            for (int cp = 0; cp < 2; ++cp) {
                uint32_t b0, b1, b2, b3;
                ldsm_x4(b0, b1, b2, b3, uW + boff[cp] + kofs);
                mma_f16(acc[2*cp],     a, b0, b1);
                mma_f16(acc[2*cp + 1], a, b2, b3);
            }
        }

        {
            int r0 = n0 + warpR * 16 + g;
            int r1 = r0 + 8;
            #pragma unroll
            for (int cf = 0; cf < 4; ++cf) {
                int cb = warpC * 32 + cf * 8 + 2 * t;
                float bx = 0.f, by = 0.f;
                if (m == 0) { bx = bias0[cb]; by = bias0[cb + 1]; }
                if (r0 < NNODES)
                    *(float2*)&out0[((size_t)r0 * MDIM + m) * CDIM + cb] =
                        make_float2(acc[cf][0] + bx, acc[cf][1] + by);
                if (r1 < NNODES)
                    *(float2*)&out0[((size_t)r1 * MDIM + m) * CDIM + cb] =
                        make_float2(acc[cf][2] + bx, acc[cf][3] + by);
            }
        }
        __syncthreads();
        buf ^= 1;
    }
}

// ---------------------------------------------------------------------------
// Channel-wise CG tensor product, 4 channels/thread (uint2 = 2x half2).
// Reads xl/xr m=1..8 only; writes all 9 m of g_xl.
// ---------------------------------------------------------------------------
__global__ __launch_bounds__(256)
void tp_kernel() {
    __shared__ float w3s[128];
    if (threadIdx.x < 128) w3s[threadIdx.x] = g_w3j[threadIdx.x];
    __syncthreads();

    int p = blockIdx.x * 256 + threadIdx.x;
    if (p >= NNODES * (CDIM / 4)) return;
    int node = p >> 5, q = p & 31;                 // q: quad-channel (4 ch)
    const uint2* XL = (const uint2*)g_xl;
    const uint2* XR = (const uint2*)g_xr;
    uint2* OUT = (uint2*)g_xl;
    size_t base = (size_t)node * (MDIM * 32) + q;  // 32 uint2 per m-row

    float2 a1[3][2], b1[3][2], a2[5][2], b2[5][2];
    #pragma unroll
    for (int i = 0; i < 3; ++i) {
        uint2 va = XL[base + (1 + i) * 32];
        uint2 vb = XR[base + (1 + i) * 32];
        a1[i][0] = __half22float2(*(__half2*)&va.x); a1[i][1] = __half22float2(*(__half2*)&va.y);
        b1[i][0] = __half22float2(*(__half2*)&vb.x); b1[i][1] = __half22float2(*(__half2*)&vb.y);
    }
    #pragma unroll
    for (int i = 0; i < 5; ++i) {
        uint2 va = XL[base + (4 + i) * 32];
        uint2 vb = XR[base + (4 + i) * 32];
        a2[i][0] = __half22float2(*(__half2*)&va.x); a2[i][1] = __half22float2(*(__half2*)&va.y);
        b2[i][0] = __half22float2(*(__half2*)&vb.x); b2[i][1] = __half22float2(*(__half2*)&vb.y);
    }

    float2 o0[2] = { {0.f,0.f}, {0.f,0.f} };
    #pragma unroll
    for (int i = 0; i < 5; ++i)
        #pragma unroll
        for (int j = 0; j < 5; ++j) {
            float w = w3s[i * 5 + j];
            #pragma unroll
            for (int h = 0; h < 2; ++h) {
                o0[h].x += w * a2[i][h].x * b2[j][h].x;
                o0[h].y += w * a2[i][h].y * b2[j][h].y;
            }
        }

    float2 o1[3][2] = {};
    #pragma unroll
    for (int i = 0; i < 3; ++i)
        #pragma unroll
        for (int j = 0; j < 5; ++j) {
            float ab[2][2];
            #pragma unroll
            for (int h = 0; h < 2; ++h) {
                ab[h][0] = a1[i][h].x * b2[j][h].x;
                ab[h][1] = a1[i][h].y * b2[j][h].y;
            }
            #pragma unroll
            for (int k = 0; k < 3; ++k) {
                float w = w3s[25 + (i * 5 + j) * 3 + k];
                #pragma unroll
                for (int h = 0; h < 2; ++h) {
                    o1[k][h].x += w * ab[h][0];
                    o1[k][h].y += w * ab[h][1];
                }
            }
        }

    float2 o2[5][2] = {};
    #pragma unroll
    for (int i = 0; i < 3; ++i)
        #pragma unroll
        for (int j = 0; j < 3; ++j) {
            float ab[2][2];
            #pragma unroll
            for (int h = 0; h < 2; ++h) {
                ab[h][0] = a1[i][h].x * b1[j][h].x;
                ab[h][1] = a1[i][h].y * b1[j][h].y;
            }
            #pragma unroll
            for (int k = 0; k < 5; ++k) {
                float w = w3s[70 + (i * 3 + j) * 5 + k];
                #pragma unroll
                for (int h = 0; h < 2; ++h) {
                    o2[k][h].x += w * ab[h][0];
                    o2[k][h].y += w * ab[h][1];
                }
            }
        }

    auto pack = [](float2 lo, float2 hi) {
        __half2 hlo = __floats2half2_rn(lo.x, lo.y);
        __half2 hhi = __floats2half2_rn(hi.x, hi.y);
        return make_uint2(*(uint32_t*)&hlo, *(uint32_t*)&hhi);
    };

    OUT[base] = pack(o0[0], o0[1]);
    #pragma unroll
    for (int k = 0; k < 3; ++k) OUT[base + (1 + k) * 32] = pack(o1[k][0], o1[k][1]);
    #pragma unroll
    for (int k = 0; k < 5; ++k) OUT[base + (4 + k) * 32] = pack(o2[k][0], o2[k][1]);
}

// ---------------------------------------------------------------------------
extern "C" void kernel_launch(void* const* d_in, const int* in_sizes, int n_in,
                              void* d_out, int out_size) {
    const float* x  = (const float*)d_in[0];
    const float* Wl = (const float*)d_in[1];
    const float* Wr = (const float*)d_in[3];
    const float* Wf = (const float*)d_in[5];
    const float* bf = (const float*)d_in[6];
    float* out = (float*)d_out;

    __half *pxl = nullptr, *pxr = nullptr;
    cudaGetSymbolAddress((void**)&pxl, g_xl);
    cudaGetSymbolAddress((void**)&pxr, g_xr);

    const int LR_SMEM = 2 * WIMG_B + AIMG_B + STG_B;   // 94720  -> 2 CTAs/SM
    const int F_SMEM  = WIMG_B + 2 * AIMG_B;           // 52224  -> 4 CTAs/SM
    cudaFuncSetAttribute(lr_gemm_kernel,
                         cudaFuncAttributeMaxDynamicSharedMemorySize, LR_SMEM);
    cudaFuncSetAttribute(f_gemm_kernel,
                         cudaFuncAttributeMaxDynamicSharedMemorySize, F_SMEM);

    w3j_init_kernel<<<3, 128>>>();
    wsplit_kernel<<<9, 256>>>(Wl, Wr, Wf);

    // left + right linears, m=1..8 only (l=0 unused by the TP; biases irrelevant)
    lr_gemm_kernel<<<dim3(GRP_LR, 8), 256, LR_SMEM>>>(x, pxl, pxr);
    // CG tensor product (fp16 in/out, 4 ch/thread)
    tp_kernel<<<(NNODES * (CDIM / 4) + 255) / 256, 256>>>();
    // final linear (fp16 input) -> fp32 d_out
    f_gemm_kernel<<<dim3(GRP_F, MDIM), 256, F_SMEM>>>(pxl, bf, out);
}

// round 14
// speedup vs baseline: 1.1178x; 1.0056x over previous
#include <cuda_runtime.h>
#include <cuda_fp16.h>
#include <cstdint>

// Problem constants
#define NNODES  50000
#define CDIM    128
#define MDIM    9
#define CHUNK   32
#define NCHUNKS ((NNODES + CHUNK - 1) / CHUNK)      // 1563
#define GRP_LR  32                                  // 32*8 = 256 CTAs (2/SM)
#define GRP_F   64                                  // 64*9 = 576 CTAs (4/SM)
#define PITCH   136                                 // fp16 pitch; 272B rows
#define WIMG_B  (128 * PITCH * 2)                   // 34816 B per 128x128 fp16 W image
#define AIMG_B  (CHUNK * PITCH * 2)                 // 8704 B per 32x128 fp16 A image
#define STG_B   (CHUNK * CDIM * 4)                  // 16384 B fp32 A stage (LR only)

// ---------------------------------------------------------------------------
// Device scratch (fp16 intermediates)
// ---------------------------------------------------------------------------
__device__ float g_w3j[128];
__device__ __align__(16) char g_wimg[9 * WIMG_B];
__device__ __half g_xl[(size_t)NNODES * MDIM * CDIM];
__device__ __half g_xr[(size_t)NNODES * MDIM * CDIM];

// ---------------------------------------------------------------------------
// HMMA + ldmatrix + cp.async helpers
// ---------------------------------------------------------------------------
__device__ __forceinline__ void mma_f16(float* d, const uint32_t* a, uint32_t b0, uint32_t b1) {
    asm volatile(
        "mma.sync.aligned.m16n8k16.row.col.f32.f16.f16.f32 "
        "{%0,%1,%2,%3}, {%4,%5,%6,%7}, {%8,%9}, {%0,%1,%2,%3};"
        : "+f"(d[0]), "+f"(d[1]), "+f"(d[2]), "+f"(d[3])
        : "r"(a[0]), "r"(a[1]), "r"(a[2]), "r"(a[3]), "r"(b0), "r"(b1));
}
__device__ __forceinline__ void ldsm_x4(uint32_t& r0, uint32_t& r1, uint32_t& r2, uint32_t& r3,
                                        uint32_t addr) {
    asm volatile("ldmatrix.sync.aligned.m8n8.x4.shared.b16 {%0,%1,%2,%3}, [%4];"
                 : "=r"(r0), "=r"(r1), "=r"(r2), "=r"(r3) : "r"(addr));
}
__device__ __forceinline__ uint32_t smem_u32(const void* p) {
    return (uint32_t)__cvta_generic_to_shared(p);
}
__device__ __forceinline__ void cp_async16(uint32_t dst, const void* src, bool valid) {
    int sz = valid ? 16 : 0;
    asm volatile("cp.async.cg.shared.global [%0], [%1], 16, %2;"
                 :: "r"(dst), "l"(src), "r"(sz));
}
__device__ __forceinline__ void cp_commit() { asm volatile("cp.async.commit_group;"); }
__device__ __forceinline__ void cp_wait0()  { asm volatile("cp.async.wait_group 0;" ::: "memory"); }
__device__ __forceinline__ void cp_wait1()  { asm volatile("cp.async.wait_group 1;" ::: "memory"); }

// ---------------------------------------------------------------------------
// Wigner-3j init — parallel (3 blocks x 128 threads)
// ---------------------------------------------------------------------------
struct C2 { double r, i; };
__device__ __forceinline__ C2 cmul(C2 a, C2 b) { return { a.r*b.r - a.i*b.i, a.r*b.i + a.i*b.r }; }
__device__ double dfact(int n) { double r = 1.0; for (int i = 2; i <= n; ++i) r *= (double)i; return r; }

__device__ double su2cg(int j1, int m1, int j2, int m2, int j3, int m3) {
    if (m3 != m1 + m2) return 0.0;
    int vmin = -j1 + j2 + m3; if (-j1 + m1 > vmin) vmin = -j1 + m1; if (0 > vmin) vmin = 0;
    int vmax = j2 + j3 + m1; if (j3 - j1 + j2 < vmax) vmax = j3 - j1 + j2; if (j3 + m3 < vmax) vmax = j3 + m3;
    double pref = sqrt((double)(2*j3+1) * dfact(j3+j1-j2) * dfact(j3-j1+j2) * dfact(j1+j2-j3)
                       / dfact(j1+j2+j3+1)
                       * dfact(j3+m3) * dfact(j3-m3)
                       / (dfact(j1-m1) * dfact(j1+m1) * dfact(j2-m2) * dfact(j2+m2)));
    double s = 0.0;
    for (int v = vmin; v <= vmax; ++v) {
        double sign = ((v + j2 + m2) & 1) ? -1.0 : 1.0;
        s += sign / dfact(v) * dfact(j2+j3+m1-v) * dfact(j1-m1+v)
             / (dfact(j3-j1+j2-v) * dfact(j3+m3-v) * dfact(v+j1-j2-m3));
    }
    return pref * s;
}

__device__ void qmat(int l, C2 Q[5][5]) {
    for (int a = 0; a < 5; ++a) for (int b = 0; b < 5; ++b) Q[a][b] = {0.0, 0.0};
    const double is2 = 0.7071067811865475244;
    for (int m = -l; m < 0; ++m) {
        Q[l+m][l-m] = { is2, 0.0 };
        Q[l+m][l+m] = { 0.0, -is2 };
    }
    Q[l][l] = { 1.0, 0.0 };
    for (int m = 1; m <= l; ++m) {
        double s = (m & 1) ? -1.0 : 1.0;
        Q[l+m][l+m] = { s * is2, 0.0 };
        Q[l+m][l-m] = { 0.0, s * is2 };
    }
    C2 f = (l == 0) ? C2{1.0, 0.0} : (l == 1) ? C2{0.0, -1.0} : C2{-1.0, 0.0};
    for (int a = 0; a < 2*l+1; ++a) for (int b = 0; b < 2*l+1; ++b) Q[a][b] = cmul(Q[a][b], f);
}

__global__ void w3j_init_kernel() {
    __shared__ double cgs[125];
    __shared__ double crs[125];
    __shared__ double red[128];

    const int tid = threadIdx.x;
    const int blk = blockIdx.x;
    const int l1 = (blk == 0) ? 2 : 1;
    const int l2 = (blk == 2) ? 1 : 2;
    const int lo = blk == 0 ? 0 : (blk == 1 ? 1 : 2);
    const double alpha = (blk == 0) ? 1.0 : (blk == 1 ? 1.7320508075688772935 : 2.2360679774997896964);
    const int off = (blk == 0) ? 0 : (blk == 1 ? 25 : 70);
    const int d1 = 2*l1+1, d2 = 2*l2+1, d3 = 2*lo+1;
    const int nel = d1 * d2 * d3;

    if (tid < nel) {
        int i = tid / (d2 * d3), k = (tid / d3) % d2, n = tid % d3;
        cgs[tid] = su2cg(l1, i - l1, l2, k - l2, lo, n - lo);
    }
    __syncthreads();

    double cr = 0.0;
    if (tid < nel) {
        C2 Q1[5][5], Q2[5][5], Q3[5][5];
        qmat(l1, Q1); qmat(l2, Q2); qmat(lo, Q3);
        int a = tid / (d2 * d3), b = (tid / d3) % d2, c = tid % d3;
        C2 s = {0.0, 0.0};
        for (int i = 0; i < d1; ++i)
            for (int k = 0; k < d2; ++k) {
                C2 q12 = cmul(Q1[i][a], Q2[k][b]);
                for (int n = 0; n < d3; ++n) {
                    double cg = cgs[(i * d2 + k) * d3 + n];
                    if (cg == 0.0) continue;
                    C2 q3c = { Q3[n][c].r, -Q3[n][c].i };
                    C2 t = cmul(q12, q3c);
                    s.r += t.r * cg; s.i += t.i * cg;
                }
            }
        cr = s.r;
        crs[tid] = cr;
    }

    red[tid] = (tid < nel) ? cr * cr : 0.0;
    __syncthreads();
    for (int stride = 64; stride > 0; stride >>= 1) {
        if (tid < stride) red[tid] += red[tid + stride];
        __syncthreads();
    }
    double inv = alpha * rsqrt(red[0]);

    if (tid < nel) g_w3j[off + tid] = (float)(crs[tid] * inv);
    if (blk == 2 && tid >= 115 && tid < 128) g_w3j[tid] = 0.0f;
}

// ---------------------------------------------------------------------------
// Weight prep: round fp32 W to fp16 image [cout][k], pitch PITCH.
// ---------------------------------------------------------------------------
__global__ void wsplit_kernel(const float* __restrict__ Wl,
                              const float* __restrict__ Wr,
                              const float* __restrict__ Wf) {
    int b = blockIdx.x;
    int which = b / 3, ll = b % 3;
    const float* W = (which == 0 ? Wl : which == 1 ? Wr : Wf) + ll * CDIM * CDIM;
    char* img = g_wimg + (size_t)b * WIMG_B;
    for (int i = threadIdx.x; i < CDIM * CDIM; i += blockDim.x) {
        int cout = i >> 7, k = i & 127;
        *(__half*)(img + (cout * PITCH + k) * 2) = __float2half_rn(W[i]);
    }
}

// ---------------------------------------------------------------------------
// LR GEMM: fp32 in, 2 fp16 outputs. m = 1..8 ONLY (l=0 of xl/xr unused by TP;
// biases bl/br touch only l=0 and are therefore irrelevant). 2 CTAs/SM.
// ---------------------------------------------------------------------------
__global__ __launch_bounds__(256, 2)
void lr_gemm_kernel(const float* __restrict__ src,
                    __half* __restrict__ out0,
                    __half* __restrict__ out1)
{
    extern __shared__ __align__(16) char smem[];
    char* Wsm   = smem;
    char* A_img = smem + 2 * WIMG_B;
    char* stg   = A_img + AIMG_B;

    const int tid = threadIdx.x, wid = tid >> 5, lane = tid & 31;
    const int g = lane >> 2, t = lane & 3;
    const int m = blockIdx.y + 1;                  // m = 1..8
    const int l = (m >= 4) ? 2 : 1;
    const int warpR = wid & 1, warpC = wid >> 1;   // 2 x 4 warps

    // Stage W images once (left = wb 0+l, right = wb 3+l)
    {
        const float4* s0 = (const float4*)(g_wimg + (size_t)l * WIMG_B);
        const float4* s1 = (const float4*)(g_wimg + (size_t)(3 + l) * WIMG_B);
        float4* d0 = (float4*)Wsm;
        float4* d1 = (float4*)(Wsm + WIMG_B);
        for (int i = tid; i < WIMG_B / 16; i += 256) { d0[i] = s0[i]; d1[i] = s1[i]; }
    }

    const int jm = lane >> 3, rr = lane & 7;
    const uint32_t aoff = (uint32_t)(((warpR * 16 + ((jm & 1) << 3) + rr) * PITCH
                                      + ((jm >> 1) << 3)) * 2);
    uint32_t boff[2];
    #pragma unroll
    for (int cp = 0; cp < 2; ++cp) {
        int n = warpC * 32 + cp * 16 + ((jm >> 1) << 3) + rr;
        boff[cp] = (uint32_t)((n * PITCH + ((jm & 1) << 3)) * 2);
    }

    const uint32_t uA = smem_u32(A_img), uW = smem_u32(Wsm), uStg = smem_u32(stg);

    auto issue_chunk = [&](int c) {
        int n0 = c * CHUNK;
        #pragma unroll
        for (int it = 0; it < 4; ++it) {
            int idx = it * 256 + tid;
            int row = idx >> 5, c4 = (idx & 31) << 2;
            int n = n0 + row;
            cp_async16(uStg + (uint32_t)idx * 16,
                       &src[((size_t)n * MDIM + m) * CDIM + c4],
                       n < NNODES);
        }
        cp_commit();
    };

    int c = blockIdx.x;
    if (c < NCHUNKS) issue_chunk(c);

    for (; c < NCHUNKS; c += GRP_LR) {
        const int n0 = c * CHUNK;
        cp_wait0();
        __syncthreads();

        #pragma unroll
        for (int it = 0; it < 4; ++it) {
            int idx = it * 256 + tid;
            int row = idx >> 5, c4 = (idx & 31) << 2;
            float4 v = *(float4*)(stg + idx * 16);
            __half2 h01 = __floats2half2_rn(v.x, v.y);
            __half2 h23 = __floats2half2_rn(v.z, v.w);
            *(uint2*)(A_img + (row * PITCH + c4) * 2) =
                make_uint2(*(uint32_t*)&h01, *(uint32_t*)&h23);
        }
        __syncthreads();

        if (c + GRP_LR < NCHUNKS) issue_chunk(c + GRP_LR);

        float acc[2][4][4];
        #pragma unroll
        for (int o = 0; o < 2; ++o)
            #pragma unroll
            for (int cf = 0; cf < 4; ++cf)
                #pragma unroll
                for (int q = 0; q < 4; ++q) acc[o][cf][q] = 0.f;

        #pragma unroll
        for (int ks = 0; ks < 8; ++ks) {
            const uint32_t kofs = (uint32_t)(ks * 32);
            uint32_t a[4];
            ldsm_x4(a[0], a[1], a[2], a[3], uA + aoff + kofs);
            #pragma unroll
            for (int o = 0; o < 2; ++o) {
                const uint32_t uWp = uW + o * WIMG_B;
                #pragma unroll
                for (int cp = 0; cp < 2; ++cp) {
                    uint32_t b0, b1, b2, b3;
                    ldsm_x4(b0, b1, b2, b3, uWp + boff[cp] + kofs);
                    mma_f16(acc[o][2*cp],     a, b0, b1);
                    mma_f16(acc[o][2*cp + 1], a, b2, b3);
                }
            }
        }

        #pragma unroll
        for (int o = 0; o < 2; ++o) {
            __half* out = o ? out1 : out0;
            int r0 = n0 + warpR * 16 + g;
            int r1 = r0 + 8;
            #pragma unroll
            for (int cf = 0; cf < 4; ++cf) {
                int cb = warpC * 32 + cf * 8 + 2 * t;
                if (r0 < NNODES) {
                    __half2 h = __floats2half2_rn(acc[o][cf][0], acc[o][cf][1]);
                    *(uint32_t*)&out[((size_t)r0 * MDIM + m) * CDIM + cb] = *(uint32_t*)&h;
                }
                if (r1 < NNODES) {
                    __half2 h = __floats2half2_rn(acc[o][cf][2], acc[o][cf][3]);
                    *(uint32_t*)&out[((size_t)r1 * MDIM + m) * CDIM + cb] = *(uint32_t*)&h;
                }
            }
        }
    }
}

// ---------------------------------------------------------------------------
// Final GEMM: fp16 in (direct cp.async, double-buffered), fp32 out. 4 CTAs/SM.
// ---------------------------------------------------------------------------
__global__ __launch_bounds__(256, 4)
void f_gemm_kernel(const __half* __restrict__ src,
                   const float* __restrict__ bias0,
                   float* __restrict__ out0)
{
    extern __shared__ __align__(16) char smem[];
    char* Wsm  = smem;
    char* Aimg[2] = { smem + WIMG_B, smem + WIMG_B + AIMG_B };

    const int tid = threadIdx.x, wid = tid >> 5, lane = tid & 31;
    const int g = lane >> 2, t = lane & 3;
    const int m = blockIdx.y;
    const int l = (m >= 4) ? 2 : (m >= 1) ? 1 : 0;
    const int warpR = wid & 1, warpC = wid >> 1;

    {
        const float4* s0 = (const float4*)(g_wimg + (size_t)(6 + l) * WIMG_B);
        float4* d0 = (float4*)Wsm;
        for (int i = tid; i < WIMG_B / 16; i += 256) d0[i] = s0[i];
    }

    const int jm = lane >> 3, rr = lane & 7;
    const uint32_t aoff = (uint32_t)(((warpR * 16 + ((jm & 1) << 3) + rr) * PITCH
                                      + ((jm >> 1) << 3)) * 2);
    uint32_t boff[2];
    #pragma unroll
    for (int cp = 0; cp < 2; ++cp) {
        int n = warpC * 32 + cp * 16 + ((jm >> 1) << 3) + rr;
        boff[cp] = (uint32_t)((n * PITCH + ((jm & 1) << 3)) * 2);
    }
    const uint32_t uW = smem_u32(Wsm);
    const uint32_t uAimg[2] = { smem_u32(Aimg[0]), smem_u32(Aimg[1]) };

    auto issue_chunk = [&](int c, int buf) {
        int n0 = c * CHUNK;
        #pragma unroll
        for (int it = 0; it < 2; ++it) {
            int idx = it * 256 + tid;
            int row = idx >> 4, c8 = (idx & 15) << 3;
            int n = n0 + row;
            cp_async16(uAimg[buf] + (uint32_t)(row * PITCH + c8) * 2,
                       &src[((size_t)n * MDIM + m) * CDIM + c8],
                       n < NNODES);
        }
        cp_commit();
    };

    int c = blockIdx.x;
    int buf = 0;
    if (c < NCHUNKS) issue_chunk(c, 0);

    for (; c < NCHUNKS; c += GRP_F) {
        const int n0 = c * CHUNK;
        bool more = (c + GRP_F < NCHUNKS);
        if (more) issue_chunk(c + GRP_F, buf ^ 1);
        if (more) cp_wait1(); else cp_wait0();
        __syncthreads();

        const uint32_t uA = uAimg[buf];
        float acc[4][4];
        #pragma unroll
        for (int cf = 0; cf < 4; ++cf)
            #pragma unroll
            for (int q = 0; q < 4; ++q) acc[cf][q] = 0.f;

        #pragma unroll
        for (int ks = 0; ks < 8; ++ks) {
            const uint32_t kofs = (uint32_t)(ks * 32);
            uint32_t a[4];
            ldsm_x4(a[0], a[1], a[2], a[3], uA + aoff + kofs);
            #pragma unroll
            for (int cp = 0; cp < 2; ++cp) {
                uint32_t b0, b1, b2, b3;
                ldsm_x4(b0, b1, b2, b3, uW + boff[cp] + kofs);
                mma_f16(acc[2*cp],     a, b0, b1);
                mma_f16(acc[2*cp + 1], a, b2, b3);
            }
        }

        {
            int r0 = n0 + warpR * 16 + g;
            int r1 = r0 + 8;
            #pragma unroll
            for (int cf = 0; cf < 4; ++cf) {
                int cb = warpC * 32 + cf * 8 + 2 * t;
                float bx = 0.f, by = 0.f;
                if (m == 0) { bx = bias0[cb]; by = bias0[cb + 1]; }
                if (r0 < NNODES)
                    *(float2*)&out0[((size_t)r0 * MDIM + m) * CDIM + cb] =
                        make_float2(acc[cf][0] + bx, acc[cf][1] + by);
                if (r1 < NNODES)
                    *(float2*)&out0[((size_t)r1 * MDIM + m) * CDIM + cb] =
                        make_float2(acc[cf][2] + bx, acc[cf][3] + by);
            }
        }
        __syncthreads();
        buf ^= 1;
    }
}

// ---------------------------------------------------------------------------
// Channel-wise CG tensor product, 4 channels/thread (uint2 = 2x half2).
// Reads xl/xr m=1..8 only; writes all 9 m of g_xl.
// ---------------------------------------------------------------------------
__global__ __launch_bounds__(256)
void tp_kernel() {
    __shared__ float w3s[128];
    if (threadIdx.x < 128) w3s[threadIdx.x] = g_w3j[threadIdx.x];
    __syncthreads();

    int p = blockIdx.x * 256 + threadIdx.x;
    if (p >= NNODES * (CDIM / 4)) return;
    int node = p >> 5, q = p & 31;                 // q: quad-channel (4 ch)
    const uint2* XL = (const uint2*)g_xl;
    const uint2* XR = (const uint2*)g_xr;
    uint2* OUT = (uint2*)g_xl;
    size_t base = (size_t)node * (MDIM * 32) + q;  // 32 uint2 per m-row

    float2 a1[3][2], b1[3][2], a2[5][2], b2[5][2];
    #pragma unroll
    for (int i = 0; i < 3; ++i) {
        uint2 va = XL[base + (1 + i) * 32];
        uint2 vb = XR[base + (1 + i) * 32];
        a1[i][0] = __half22float2(*(__half2*)&va.x); a1[i][1] = __half22float2(*(__half2*)&va.y);
        b1[i][0] = __half22float2(*(__half2*)&vb.x); b1[i][1] = __half22float2(*(__half2*)&vb.y);
    }
    #pragma unroll
    for (int i = 0; i < 5; ++i) {
        uint2 va = XL[base + (4 + i) * 32];
        uint2 vb = XR[base + (4 + i) * 32];
        a2[i][0] = __half22float2(*(__half2*)&va.x); a2[i][1] = __half22float2(*(__half2*)&va.y);
        b2[i][0] = __half22float2(*(__half2*)&vb.x); b2[i][1] = __half22float2(*(__half2*)&vb.y);
    }

    float2 o0[2] = { {0.f,0.f}, {0.f,0.f} };
    #pragma unroll
    for (int i = 0; i < 5; ++i)
        #pragma unroll
        for (int j = 0; j < 5; ++j) {
            float w = w3s[i * 5 + j];
            #pragma unroll
            for (int h = 0; h < 2; ++h) {
                o0[h].x += w * a2[i][h].x * b2[j][h].x;
                o0[h].y += w * a2[i][h].y * b2[j][h].y;
            }
        }

    float2 o1[3][2] = {};
    #pragma unroll
    for (int i = 0; i < 3; ++i)
        #pragma unroll
        for (int j = 0; j < 5; ++j) {
            float ab[2][2];
            #pragma unroll
            for (int h = 0; h < 2; ++h) {
                ab[h][0] = a1[i][h].x * b2[j][h].x;
                ab[h][1] = a1[i][h].y * b2[j][h].y;
            }
            #pragma unroll
            for (int k = 0; k < 3; ++k) {
                float w = w3s[25 + (i * 5 + j) * 3 + k];
                #pragma unroll
                for (int h = 0; h < 2; ++h) {
                    o1[k][h].x += w * ab[h][0];
                    o1[k][h].y += w * ab[h][1];
                }
            }
        }

    float2 o2[5][2] = {};
    #pragma unroll
    for (int i = 0; i < 3; ++i)
        #pragma unroll
        for (int j = 0; j < 3; ++j) {
            float ab[2][2];
            #pragma unroll
            for (int h = 0; h < 2; ++h) {
                ab[h][0] = a1[i][h].x * b1[j][h].x;
                ab[h][1] = a1[i][h].y * b1[j][h].y;
            }
            #pragma unroll
            for (int k = 0; k < 5; ++k) {
                float w = w3s[70 + (i * 3 + j) * 5 + k];
                #pragma unroll
                for (int h = 0; h < 2; ++h) {
                    o2[k][h].x += w * ab[h][0];
                    o2[k][h].y += w * ab[h][1];
                }
            }
        }

    auto pack = [](float2 lo, float2 hi) {
        __half2 hlo = __floats2half2_rn(lo.x, lo.y);
        __half2 hhi = __floats2half2_rn(hi.x, hi.y);
        return make_uint2(*(uint32_t*)&hlo, *(uint32_t*)&hhi);
    };

    OUT[base] = pack(o0[0], o0[1]);
    #pragma unroll
    for (int k = 0; k < 3; ++k) OUT[base + (1 + k) * 32] = pack(o1[k][0], o1[k][1]);
    #pragma unroll
    for (int k = 0; k < 5; ++k) OUT[base + (4 + k) * 32] = pack(o2[k][0], o2[k][1]);
}

// ---------------------------------------------------------------------------
extern "C" void kernel_launch(void* const* d_in, const int* in_sizes, int n_in,
                              void* d_out, int out_size) {
    const float* x  = (const float*)d_in[0];
    const float* Wl = (const float*)d_in[1];
    const float* Wr = (const float*)d_in[3];
    const float* Wf = (const float*)d_in[5];
    const float* bf = (const float*)d_in[6];
    float* out = (float*)d_out;

    __half *pxl = nullptr, *pxr = nullptr;
    cudaGetSymbolAddress((void**)&pxl, g_xl);
    cudaGetSymbolAddress((void**)&pxr, g_xr);

    const int LR_SMEM = 2 * WIMG_B + AIMG_B + STG_B;   // 94720  -> 2 CTAs/SM
    const int F_SMEM  = WIMG_B + 2 * AIMG_B;           // 52224  -> 4 CTAs/SM
    cudaFuncSetAttribute(lr_gemm_kernel,
                         cudaFuncAttributeMaxDynamicSharedMemorySize, LR_SMEM);
    cudaFuncSetAttribute(f_gemm_kernel,
                         cudaFuncAttributeMaxDynamicSharedMemorySize, F_SMEM);

    w3j_init_kernel<<<3, 128>>>();
    wsplit_kernel<<<9, 256>>>(Wl, Wr, Wf);

    // left + right linears, m=1..8 only (l=0 unused by the TP; biases irrelevant)
    lr_gemm_kernel<<<dim3(GRP_LR, 8), 256, LR_SMEM>>>(x, pxl, pxr);
    // CG tensor product (fp16 in/out, 4 ch/thread)
    tp_kernel<<<(NNODES * (CDIM / 4) + 255) / 256, 256>>>();
    // final linear (fp16 input) -> fp32 d_out
    f_gemm_kernel<<<dim3(GRP_F, MDIM), 256, F_SMEM>>>(pxl, bf, out);
}

// round 15
// speedup vs baseline: 1.3016x; 1.1644x over previous
#include <cuda_runtime.h>
#include <cuda_fp16.h>
#include <cstdint>

// Problem constants
#define NNODES  50000
#define CDIM    128
#define MDIM    9
#define CHUNK   32
#define NCHUNKS ((NNODES + CHUNK - 1) / CHUNK)      // 1563
#define GRP_LR  37                                  // 37*8 = 296 CTAs (2/SM, one wave)
#define GRP_F   33                                  // 33*9 = 297 CTAs (2/SM, one wave)
#define PITCH   136                                 // fp16 pitch; 272B rows
#define WIMG_B  (128 * PITCH * 2)                   // 34816 B per 128x128 fp16 W image
#define AIMG_B  (CHUNK * PITCH * 2)                 // 8704 B per 32x128 fp16 A image
#define STG_B   (CHUNK * CDIM * 4)                  // 16384 B fp32 A stage (LR only)

// ---------------------------------------------------------------------------
// Device scratch (fp16 intermediates)
// ---------------------------------------------------------------------------
__device__ float g_w3j[128];
__device__ __align__(16) char g_wimg[9 * WIMG_B];
__device__ __half g_xl[(size_t)NNODES * MDIM * CDIM];
__device__ __half g_xr[(size_t)NNODES * MDIM * CDIM];

// ---------------------------------------------------------------------------
// HMMA + ldmatrix + cp.async helpers
// ---------------------------------------------------------------------------
__device__ __forceinline__ void mma_f16(float* d, const uint32_t* a, uint32_t b0, uint32_t b1) {
    asm volatile(
        "mma.sync.aligned.m16n8k16.row.col.f32.f16.f16.f32 "
        "{%0,%1,%2,%3}, {%4,%5,%6,%7}, {%8,%9}, {%0,%1,%2,%3};"
        : "+f"(d[0]), "+f"(d[1]), "+f"(d[2]), "+f"(d[3])
        : "r"(a[0]), "r"(a[1]), "r"(a[2]), "r"(a[3]), "r"(b0), "r"(b1));
}
__device__ __forceinline__ void ldsm_x4(uint32_t& r0, uint32_t& r1, uint32_t& r2, uint32_t& r3,
                                        uint32_t addr) {
    asm volatile("ldmatrix.sync.aligned.m8n8.x4.shared.b16 {%0,%1,%2,%3}, [%4];"
                 : "=r"(r0), "=r"(r1), "=r"(r2), "=r"(r3) : "r"(addr));
}
__device__ __forceinline__ uint32_t smem_u32(const void* p) {
    return (uint32_t)__cvta_generic_to_shared(p);
}
__device__ __forceinline__ void cp_async16(uint32_t dst, const void* src, bool valid) {
    int sz = valid ? 16 : 0;
    asm volatile("cp.async.cg.shared.global [%0], [%1], 16, %2;"
                 :: "r"(dst), "l"(src), "r"(sz));
}
__device__ __forceinline__ void cp_commit() { asm volatile("cp.async.commit_group;"); }
__device__ __forceinline__ void cp_wait0()  { asm volatile("cp.async.wait_group 0;" ::: "memory"); }
__device__ __forceinline__ void cp_wait1()  { asm volatile("cp.async.wait_group 1;" ::: "memory"); }

// ---------------------------------------------------------------------------
// Wigner-3j init — parallel (3 blocks x 128 threads)
// ---------------------------------------------------------------------------
struct C2 { double r, i; };
__device__ __forceinline__ C2 cmul(C2 a, C2 b) { return { a.r*b.r - a.i*b.i, a.r*b.i + a.i*b.r }; }
__device__ double dfact(int n) { double r = 1.0; for (int i = 2; i <= n; ++i) r *= (double)i; return r; }

__device__ double su2cg(int j1, int m1, int j2, int m2, int j3, int m3) {
    if (m3 != m1 + m2) return 0.0;
    int vmin = -j1 + j2 + m3; if (-j1 + m1 > vmin) vmin = -j1 + m1; if (0 > vmin) vmin = 0;
    int vmax = j2 + j3 + m1; if (j3 - j1 + j2 < vmax) vmax = j3 - j1 + j2; if (j3 + m3 < vmax) vmax = j3 + m3;
    double pref = sqrt((double)(2*j3+1) * dfact(j3+j1-j2) * dfact(j3-j1+j2) * dfact(j1+j2-j3)
                       / dfact(j1+j2+j3+1)
                       * dfact(j3+m3) * dfact(j3-m3)
                       / (dfact(j1-m1) * dfact(j1+m1) * dfact(j2-m2) * dfact(j2+m2)));
    double s = 0.0;
    for (int v = vmin; v <= vmax; ++v) {
        double sign = ((v + j2 + m2) & 1) ? -1.0 : 1.0;
        s += sign / dfact(v) * dfact(j2+j3+m1-v) * dfact(j1-m1+v)
             / (dfact(j3-j1+j2-v) * dfact(j3+m3-v) * dfact(v+j1-j2-m3));
    }
    return pref * s;
}

__device__ void qmat(int l, C2 Q[5][5]) {
    for (int a = 0; a < 5; ++a) for (int b = 0; b < 5; ++b) Q[a][b] = {0.0, 0.0};
    const double is2 = 0.7071067811865475244;
    for (int m = -l; m < 0; ++m) {
        Q[l+m][l-m] = { is2, 0.0 };
        Q[l+m][l+m] = { 0.0, -is2 };
    }
    Q[l][l] = { 1.0, 0.0 };
    for (int m = 1; m <= l; ++m) {
        double s = (m & 1) ? -1.0 : 1.0;
        Q[l+m][l+m] = { s * is2, 0.0 };
        Q[l+m][l-m] = { 0.0, s * is2 };
    }
    C2 f = (l == 0) ? C2{1.0, 0.0} : (l == 1) ? C2{0.0, -1.0} : C2{-1.0, 0.0};
    for (int a = 0; a < 2*l+1; ++a) for (int b = 0; b < 2*l+1; ++b) Q[a][b] = cmul(Q[a][b], f);
}

__global__ void w3j_init_kernel() {
    __shared__ double cgs[125];
    __shared__ double crs[125];
    __shared__ double red[128];

    const int tid = threadIdx.x;
    const int blk = blockIdx.x;
    const int l1 = (blk == 0) ? 2 : 1;
    const int l2 = (blk == 2) ? 1 : 2;
    const int lo = blk == 0 ? 0 : (blk == 1 ? 1 : 2);
    const double alpha = (blk == 0) ? 1.0 : (blk == 1 ? 1.7320508075688772935 : 2.2360679774997896964);
    const int off = (blk == 0) ? 0 : (blk == 1 ? 25 : 70);
    const int d1 = 2*l1+1, d2 = 2*l2+1, d3 = 2*lo+1;
    const int nel = d1 * d2 * d3;

    if (tid < nel) {
        int i = tid / (d2 * d3), k = (tid / d3) % d2, n = tid % d3;
        cgs[tid] = su2cg(l1, i - l1, l2, k - l2, lo, n - lo);
    }
    __syncthreads();

    double cr = 0.0;
    if (tid < nel) {
        C2 Q1[5][5], Q2[5][5], Q3[5][5];
        qmat(l1, Q1); qmat(l2, Q2); qmat(lo, Q3);
        int a = tid / (d2 * d3), b = (tid / d3) % d2, c = tid % d3;
        C2 s = {0.0, 0.0};
        for (int i = 0; i < d1; ++i)
            for (int k = 0; k < d2; ++k) {
                C2 q12 = cmul(Q1[i][a], Q2[k][b]);
                for (int n = 0; n < d3; ++n) {
                    double cg = cgs[(i * d2 + k) * d3 + n];
                    if (cg == 0.0) continue;
                    C2 q3c = { Q3[n][c].r, -Q3[n][c].i };
                    C2 t = cmul(q12, q3c);
                    s.r += t.r * cg; s.i += t.i * cg;
                }
            }
        cr = s.r;
        crs[tid] = cr;
    }

    red[tid] = (tid < nel) ? cr * cr : 0.0;
    __syncthreads();
    for (int stride = 64; stride > 0; stride >>= 1) {
        if (tid < stride) red[tid] += red[tid + stride];
        __syncthreads();
    }
    double inv = alpha * rsqrt(red[0]);

    if (tid < nel) g_w3j[off + tid] = (float)(crs[tid] * inv);
    if (blk == 2 && tid >= 115 && tid < 128) g_w3j[tid] = 0.0f;
}

// ---------------------------------------------------------------------------
// Weight prep: round fp32 W to fp16 image [cout][k], pitch PITCH.
// ---------------------------------------------------------------------------
__global__ void wsplit_kernel(const float* __restrict__ Wl,
                              const float* __restrict__ Wr,
                              const float* __restrict__ Wf) {
    int b = blockIdx.x;
    int which = b / 3, ll = b % 3;
    const float* W = (which == 0 ? Wl : which == 1 ? Wr : Wf) + ll * CDIM * CDIM;
    char* img = g_wimg + (size_t)b * WIMG_B;
    for (int i = threadIdx.x; i < CDIM * CDIM; i += blockDim.x) {
        int cout = i >> 7, k = i & 127;
        *(__half*)(img + (cout * PITCH + k) * 2) = __float2half_rn(W[i]);
    }
}

// ---------------------------------------------------------------------------
// LR GEMM: fp32 in, 2 fp16 outputs, m = 1..8 only. 2 CTAs/SM.
// Left-output W fragments cached in registers (64 regs); right via ldsm.
// ---------------------------------------------------------------------------
__global__ __launch_bounds__(256, 2)
void lr_gemm_kernel(const float* __restrict__ src,
                    __half* __restrict__ out0,
                    __half* __restrict__ out1)
{
    extern __shared__ __align__(16) char smem[];
    char* Wsm   = smem;
    char* A_img = smem + 2 * WIMG_B;
    char* stg   = A_img + AIMG_B;

    const int tid = threadIdx.x, wid = tid >> 5, lane = tid & 31;
    const int g = lane >> 2, t = lane & 3;
    const int m = blockIdx.y + 1;                  // m = 1..8
    const int l = (m >= 4) ? 2 : 1;
    const int warpR = wid & 1, warpC = wid >> 1;   // 2 x 4 warps

    // Stage W images once (left = wb 0+l, right = wb 3+l)
    {
        const float4* s0 = (const float4*)(g_wimg + (size_t)l * WIMG_B);
        const float4* s1 = (const float4*)(g_wimg + (size_t)(3 + l) * WIMG_B);
        float4* d0 = (float4*)Wsm;
        float4* d1 = (float4*)(Wsm + WIMG_B);
        for (int i = tid; i < WIMG_B / 16; i += 256) { d0[i] = s0[i]; d1[i] = s1[i]; }
    }

    const int jm = lane >> 3, rr = lane & 7;
    const uint32_t aoff = (uint32_t)(((warpR * 16 + ((jm & 1) << 3) + rr) * PITCH
                                      + ((jm >> 1) << 3)) * 2);
    uint32_t boff[2];
    #pragma unroll
    for (int cp = 0; cp < 2; ++cp) {
        int n = warpC * 32 + cp * 16 + ((jm >> 1) << 3) + rr;
        boff[cp] = (uint32_t)((n * PITCH + ((jm & 1) << 3)) * 2);
    }

    const uint32_t uA = smem_u32(A_img), uW = smem_u32(Wsm), uStg = smem_u32(stg);

    auto issue_chunk = [&](int c) {
        int n0 = c * CHUNK;
        #pragma unroll
        for (int it = 0; it < 4; ++it) {
            int idx = it * 256 + tid;
            int row = idx >> 5, c4 = (idx & 31) << 2;
            int n = n0 + row;
            cp_async16(uStg + (uint32_t)idx * 16,
                       &src[((size_t)n * MDIM + m) * CDIM + c4],
                       n < NNODES);
        }
        cp_commit();
    };

    int c = blockIdx.x;
    if (c < NCHUNKS) issue_chunk(c);

    __syncthreads();   // W staged before register-caching left-B frags

    // Cache LEFT W fragments in registers: [ks][cp][4] = 64 regs
    uint32_t BL[8][2][4];
    #pragma unroll
    for (int ks = 0; ks < 8; ++ks) {
        const uint32_t kofs = (uint32_t)(ks * 32);
        #pragma unroll
        for (int cp = 0; cp < 2; ++cp)
            ldsm_x4(BL[ks][cp][0], BL[ks][cp][1], BL[ks][cp][2], BL[ks][cp][3],
                    uW + boff[cp] + kofs);
    }

    for (; c < NCHUNKS; c += GRP_LR) {
        const int n0 = c * CHUNK;
        cp_wait0();
        __syncthreads();

        #pragma unroll
        for (int it = 0; it < 4; ++it) {
            int idx = it * 256 + tid;
            int row = idx >> 5, c4 = (idx & 31) << 2;
            float4 v = *(float4*)(stg + idx * 16);
            __half2 h01 = __floats2half2_rn(v.x, v.y);
            __half2 h23 = __floats2half2_rn(v.z, v.w);
            *(uint2*)(A_img + (row * PITCH + c4) * 2) =
                make_uint2(*(uint32_t*)&h01, *(uint32_t*)&h23);
        }
        __syncthreads();

        if (c + GRP_LR < NCHUNKS) issue_chunk(c + GRP_LR);

        float acc[2][4][4];
        #pragma unroll
        for (int o = 0; o < 2; ++o)
            #pragma unroll
            for (int cf = 0; cf < 4; ++cf)
                #pragma unroll
                for (int q = 0; q < 4; ++q) acc[o][cf][q] = 0.f;

        #pragma unroll
        for (int ks = 0; ks < 8; ++ks) {
            const uint32_t kofs = (uint32_t)(ks * 32);
            uint32_t a[4];
            ldsm_x4(a[0], a[1], a[2], a[3], uA + aoff + kofs);
            // left output: B from registers
            #pragma unroll
            for (int cp = 0; cp < 2; ++cp) {
                mma_f16(acc[0][2*cp],     a, BL[ks][cp][0], BL[ks][cp][1]);
                mma_f16(acc[0][2*cp + 1], a, BL[ks][cp][2], BL[ks][cp][3]);
            }
            // right output: B via ldsm
            #pragma unroll
            for (int cp = 0; cp < 2; ++cp) {
                uint32_t b0, b1, b2, b3;
                ldsm_x4(b0, b1, b2, b3, uW + WIMG_B + boff[cp] + kofs);
                mma_f16(acc[1][2*cp],     a, b0, b1);
                mma_f16(acc[1][2*cp + 1], a, b2, b3);
            }
        }

        #pragma unroll
        for (int o = 0; o < 2; ++o) {
            __half* out = o ? out1 : out0;
            int r0 = n0 + warpR * 16 + g;
            int r1 = r0 + 8;
            #pragma unroll
            for (int cf = 0; cf < 4; ++cf) {
                int cb = warpC * 32 + cf * 8 + 2 * t;
                if (r0 < NNODES) {
                    __half2 h = __floats2half2_rn(acc[o][cf][0], acc[o][cf][1]);
                    *(uint32_t*)&out[((size_t)r0 * MDIM + m) * CDIM + cb] = *(uint32_t*)&h;
                }
                if (r1 < NNODES) {
                    __half2 h = __floats2half2_rn(acc[o][cf][2], acc[o][cf][3]);
                    *(uint32_t*)&out[((size_t)r1 * MDIM + m) * CDIM + cb] = *(uint32_t*)&h;
                }
            }
        }
    }
}

// ---------------------------------------------------------------------------
// Final GEMM: fp16 in (direct cp.async, double-buffered), fp32 out. 2 CTAs/SM.
// ALL W fragments cached in registers (64 regs); mainloop LDSM = A only.
// ---------------------------------------------------------------------------
__global__ __launch_bounds__(256, 2)
void f_gemm_kernel(const __half* __restrict__ src,
                   const float* __restrict__ bias0,
                   float* __restrict__ out0)
{
    extern __shared__ __align__(16) char smem[];
    char* Wsm  = smem;
    char* Aimg[2] = { smem + WIMG_B, smem + WIMG_B + AIMG_B };

    const int tid = threadIdx.x, wid = tid >> 5, lane = tid & 31;
    const int g = lane >> 2, t = lane & 3;
    const int m = blockIdx.y;
    const int l = (m >= 4) ? 2 : (m >= 1) ? 1 : 0;
    const int warpR = wid & 1, warpC = wid >> 1;

    {
        const float4* s0 = (const float4*)(g_wimg + (size_t)(6 + l) * WIMG_B);
        float4* d0 = (float4*)Wsm;
        for (int i = tid; i < WIMG_B / 16; i += 256) d0[i] = s0[i];
    }

    const int jm = lane >> 3, rr = lane & 7;
    const uint32_t aoff = (uint32_t)(((warpR * 16 + ((jm & 1) << 3) + rr) * PITCH
                                      + ((jm >> 1) << 3)) * 2);
    uint32_t boff[2];
    #pragma unroll
    for (int cp = 0; cp < 2; ++cp) {
        int n = warpC * 32 + cp * 16 + ((jm >> 1) << 3) + rr;
        boff[cp] = (uint32_t)((n * PITCH + ((jm & 1) << 3)) * 2);
    }
    const uint32_t uW = smem_u32(Wsm);
    const uint32_t uAimg[2] = { smem_u32(Aimg[0]), smem_u32(Aimg[1]) };

    auto issue_chunk = [&](int c, int buf) {
        int n0 = c * CHUNK;
        #pragma unroll
        for (int it = 0; it < 2; ++it) {
            int idx = it * 256 + tid;
            int row = idx >> 4, c8 = (idx & 15) << 3;
            int n = n0 + row;
            cp_async16(uAimg[buf] + (uint32_t)(row * PITCH + c8) * 2,
                       &src[((size_t)n * MDIM + m) * CDIM + c8],
                       n < NNODES);
        }
        cp_commit();
    };

    int c = blockIdx.x;
    int buf = 0;
    if (c < NCHUNKS) issue_chunk(c, 0);

    __syncthreads();   // W staged

    // Cache ALL W fragments: [ks][cp][4] = 64 regs
    uint32_t B[8][2][4];
    #pragma unroll
    for (int ks = 0; ks < 8; ++ks) {
        const uint32_t kofs = (uint32_t)(ks * 32);
        #pragma unroll
        for (int cp = 0; cp < 2; ++cp)
            ldsm_x4(B[ks][cp][0], B[ks][cp][1], B[ks][cp][2], B[ks][cp][3],
                    uW + boff[cp] + kofs);
    }

    for (; c < NCHUNKS; c += GRP_F) {
        const int n0 = c * CHUNK;
        bool more = (c + GRP_F < NCHUNKS);
        if (more) issue_chunk(c + GRP_F, buf ^ 1);
        if (more) cp_wait1(); else cp_wait0();
        __syncthreads();

        const uint32_t uA = uAimg[buf];
        float acc[4][4];
        #pragma unroll
        for (int cf = 0; cf < 4; ++cf)
            #pragma unroll
            for (int q = 0; q < 4; ++q) acc[cf][q] = 0.f;

        #pragma unroll
        for (int ks = 0; ks < 8; ++ks) {
            const uint32_t kofs = (uint32_t)(ks * 32);
            uint32_t a[4];
            ldsm_x4(a[0], a[1], a[2], a[3], uA + aoff + kofs);
            #pragma unroll
            for (int cp = 0; cp < 2; ++cp) {
                mma_f16(acc[2*cp],     a, B[ks][cp][0], B[ks][cp][1]);
                mma_f16(acc[2*cp + 1], a, B[ks][cp][2], B[ks][cp][3]);
            }
        }

        {
            int r0 = n0 + warpR * 16 + g;
            int r1 = r0 + 8;
            #pragma unroll
            for (int cf = 0; cf < 4; ++cf) {
                int cb = warpC * 32 + cf * 8 + 2 * t;
                float bx = 0.f, by = 0.f;
                if (m == 0) { bx = bias0[cb]; by = bias0[cb + 1]; }
                if (r0 < NNODES)
                    *(float2*)&out0[((size_t)r0 * MDIM + m) * CDIM + cb] =
                        make_float2(acc[cf][0] + bx, acc[cf][1] + by);
                if (r1 < NNODES)
                    *(float2*)&out0[((size_t)r1 * MDIM + m) * CDIM + cb] =
                        make_float2(acc[cf][2] + bx, acc[cf][3] + by);
            }
        }
        __syncthreads();
        buf ^= 1;
    }
}

// ---------------------------------------------------------------------------
// Channel-wise CG tensor product, 4 channels/thread (uint2 = 2x half2).
// ---------------------------------------------------------------------------
__global__ __launch_bounds__(256)
void tp_kernel() {
    __shared__ float w3s[128];
    if (threadIdx.x < 128) w3s[threadIdx.x] = g_w3j[threadIdx.x];
    __syncthreads();

    int p = blockIdx.x * 256 + threadIdx.x;
    if (p >= NNODES * (CDIM / 4)) return;
    int node = p >> 5, q = p & 31;
    const uint2* XL = (const uint2*)g_xl;
    const uint2* XR = (const uint2*)g_xr;
    uint2* OUT = (uint2*)g_xl;
    size_t base = (size_t)node * (MDIM * 32) + q;

    float2 a1[3][2], b1[3][2], a2[5][2], b2[5][2];
    #pragma unroll
    for (int i = 0; i < 3; ++i) {
        uint2 va = XL[base + (1 + i) * 32];
        uint2 vb = XR[base + (1 + i) * 32];
        a1[i][0] = __half22float2(*(__half2*)&va.x); a1[i][1] = __half22float2(*(__half2*)&va.y);
        b1[i][0] = __half22float2(*(__half2*)&vb.x); b1[i][1] = __half22float2(*(__half2*)&vb.y);
    }
    #pragma unroll
    for (int i = 0; i < 5; ++i) {
        uint2 va = XL[base + (4 + i) * 32];
        uint2 vb = XR[base + (4 + i) * 32];
        a2[i][0] = __half22float2(*(__half2*)&va.x); a2[i][1] = __half22float2(*(__half2*)&va.y);
        b2[i][0] = __half22float2(*(__half2*)&vb.x); b2[i][1] = __half22float2(*(__half2*)&vb.y);
    }

    float2 o0[2] = { {0.f,0.f}, {0.f,0.f} };
    #pragma unroll
    for (int i = 0; i < 5; ++i)
        #pragma unroll
        for (int j = 0; j < 5; ++j) {
            float w = w3s[i * 5 + j];
            #pragma unroll
            for (int h = 0; h < 2; ++h) {
                o0[h].x += w * a2[i][h].x * b2[j][h].x;
                o0[h].y += w * a2[i][h].y * b2[j][h].y;
            }
        }

    float2 o1[3][2] = {};
    #pragma unroll
    for (int i = 0; i < 3; ++i)
        #pragma unroll
        for (int j = 0; j < 5; ++j) {
            float ab[2][2];
            #pragma unroll
            for (int h = 0; h < 2; ++h) {
                ab[h][0] = a1[i][h].x * b2[j][h].x;
                ab[h][1] = a1[i][h].y * b2[j][h].y;
            }
            #pragma unroll
            for (int k = 0; k < 3; ++k) {
                float w = w3s[25 + (i * 5 + j) * 3 + k];
                #pragma unroll
                for (int h = 0; h < 2; ++h) {
                    o1[k][h].x += w * ab[h][0];
                    o1[k][h].y += w * ab[h][1];
                }
            }
        }

    float2 o2[5][2] = {};
    #pragma unroll
    for (int i = 0; i < 3; ++i)
        #pragma unroll
        for (int j = 0; j < 3; ++j) {
            float ab[2][2];
            #pragma unroll
            for (int h = 0; h < 2; ++h) {
                ab[h][0] = a1[i][h].x * b1[j][h].x;
                ab[h][1] = a1[i][h].y * b1[j][h].y;
            }
            #pragma unroll
            for (int k = 0; k < 5; ++k) {
                float w = w3s[70 + (i * 3 + j) * 5 + k];
                #pragma unroll
                for (int h = 0; h < 2; ++h) {
                    o2[k][h].x += w * ab[h][0];
                    o2[k][h].y += w * ab[h][1];
                }
            }
        }

    auto pack = [](float2 lo, float2 hi) {
        __half2 hlo = __floats2half2_rn(lo.x, lo.y);
        __half2 hhi = __floats2half2_rn(hi.x, hi.y);
        return make_uint2(*(uint32_t*)&hlo, *(uint32_t*)&hhi);
    };

    OUT[base] = pack(o0[0], o0[1]);
    #pragma unroll
    for (int k = 0; k < 3; ++k) OUT[base + (1 + k) * 32] = pack(o1[k][0], o1[k][1]);
    #pragma unroll
    for (int k = 0; k < 5; ++k) OUT[base + (4 + k) * 32] = pack(o2[k][0], o2[k][1]);
}

// ---------------------------------------------------------------------------
extern "C" void kernel_launch(void* const* d_in, const int* in_sizes, int n_in,
                              void* d_out, int out_size) {
    const float* x  = (const float*)d_in[0];
    const float* Wl = (const float*)d_in[1];
    const float* Wr = (const float*)d_in[3];
    const float* Wf = (const float*)d_in[5];
    const float* bf = (const float*)d_in[6];
    float* out = (float*)d_out;

    __half *pxl = nullptr, *pxr = nullptr;
    cudaGetSymbolAddress((void**)&pxl, g_xl);
    cudaGetSymbolAddress((void**)&pxr, g_xr);

    const int LR_SMEM = 2 * WIMG_B + AIMG_B + STG_B;   // 94720  -> 2 CTAs/SM
    const int F_SMEM  = WIMG_B + 2 * AIMG_B;           // 52224
    cudaFuncSetAttribute(lr_gemm_kernel,
                         cudaFuncAttributeMaxDynamicSharedMemorySize, LR_SMEM);
    cudaFuncSetAttribute(f_gemm_kernel,
                         cudaFuncAttributeMaxDynamicSharedMemorySize, F_SMEM);

    w3j_init_kernel<<<3, 128>>>();
    wsplit_kernel<<<9, 256>>>(Wl, Wr, Wf);

    // left + right linears, m=1..8 only
    lr_gemm_kernel<<<dim3(GRP_LR, 8), 256, LR_SMEM>>>(x, pxl, pxr);
    // CG tensor product (fp16 in/out, 4 ch/thread)
    tp_kernel<<<(NNODES * (CDIM / 4) + 255) / 256, 256>>>();
    // final linear (fp16 input) -> fp32 d_out
    f_gemm_kernel<<<dim3(GRP_F, MDIM), 256, F_SMEM>>>(pxl, bf, out);
}

// round 16
// speedup vs baseline: 1.3228x; 1.0162x over previous
#include <cuda_runtime.h>
#include <cuda_fp16.h>
#include <cstdint>

// Problem constants
#define NNODES  50000
#define CDIM    128
#define MDIM    9
#define CHUNK   32
#define NCHUNKS ((NNODES + CHUNK - 1) / CHUNK)      // 1563
#define GRP_LR  37                                  // 37*8 = 296 CTAs (2/SM, one wave)
#define GRP_F   33                                  // 33*9 = 297 CTAs (2/SM, one wave)
#define PITCH   136                                 // fp16 pitch; 272B rows
#define WIMG_B  (128 * PITCH * 2)                   // 34816 B per 128x128 fp16 W image
#define AIMG_B  (CHUNK * PITCH * 2)                 // 8704 B per 32x128 fp16 A image
#define STG_B   (CHUNK * CDIM * 4)                  // 16384 B fp32 A stage (LR only)

typedef unsigned long long ull;

// ---------------------------------------------------------------------------
// Device scratch (fp16 intermediates)
// ---------------------------------------------------------------------------
__device__ float g_w3j[128];
__device__ __align__(16) char g_wimg[9 * WIMG_B];
__device__ __half g_xl[(size_t)NNODES * MDIM * CDIM];
__device__ __half g_xr[(size_t)NNODES * MDIM * CDIM];

// ---------------------------------------------------------------------------
// HMMA + ldmatrix + cp.async + f32x2 helpers
// ---------------------------------------------------------------------------
__device__ __forceinline__ void mma_f16(float* d, const uint32_t* a, uint32_t b0, uint32_t b1) {
    asm volatile(
        "mma.sync.aligned.m16n8k16.row.col.f32.f16.f16.f32 "
        "{%0,%1,%2,%3}, {%4,%5,%6,%7}, {%8,%9}, {%0,%1,%2,%3};"
        : "+f"(d[0]), "+f"(d[1]), "+f"(d[2]), "+f"(d[3])
        : "r"(a[0]), "r"(a[1]), "r"(a[2]), "r"(a[3]), "r"(b0), "r"(b1));
}
__device__ __forceinline__ void ldsm_x4(uint32_t& r0, uint32_t& r1, uint32_t& r2, uint32_t& r3,
                                        uint32_t addr) {
    asm volatile("ldmatrix.sync.aligned.m8n8.x4.shared.b16 {%0,%1,%2,%3}, [%4];"
                 : "=r"(r0), "=r"(r1), "=r"(r2), "=r"(r3) : "r"(addr));
}
__device__ __forceinline__ uint32_t smem_u32(const void* p) {
    return (uint32_t)__cvta_generic_to_shared(p);
}
__device__ __forceinline__ void cp_async16(uint32_t dst, const void* src, bool valid) {
    int sz = valid ? 16 : 0;
    asm volatile("cp.async.cg.shared.global [%0], [%1], 16, %2;"
                 :: "r"(dst), "l"(src), "r"(sz));
}
__device__ __forceinline__ void cp_commit() { asm volatile("cp.async.commit_group;"); }
__device__ __forceinline__ void cp_wait0()  { asm volatile("cp.async.wait_group 0;" ::: "memory"); }
__device__ __forceinline__ void cp_wait1()  { asm volatile("cp.async.wait_group 1;" ::: "memory"); }

__device__ __forceinline__ ull pack2(float x, float y) {
    ull r; asm("mov.b64 %0, {%1, %2};" : "=l"(r) : "f"(x), "f"(y)); return r;
}
__device__ __forceinline__ void unpack2(ull v, float& x, float& y) {
    asm("mov.b64 {%0, %1}, %2;" : "=f"(x), "=f"(y) : "l"(v));
}
__device__ __forceinline__ void ffma2(ull& d, ull a, ull b) {
    asm("fma.rn.f32x2 %0, %1, %2, %0;" : "+l"(d) : "l"(a), "l"(b));
}
__device__ __forceinline__ ull mul2(ull a, ull b) {
    ull r; asm("mul.rn.f32x2 %0, %1, %2;" : "=l"(r) : "l"(a), "l"(b)); return r;
}

// ---------------------------------------------------------------------------
// Wigner-3j init — parallel (3 blocks x 128 threads)
// ---------------------------------------------------------------------------
struct C2 { double r, i; };
__device__ __forceinline__ C2 cmul(C2 a, C2 b) { return { a.r*b.r - a.i*b.i, a.r*b.i + a.i*b.r }; }
__device__ double dfact(int n) { double r = 1.0; for (int i = 2; i <= n; ++i) r *= (double)i; return r; }

__device__ double su2cg(int j1, int m1, int j2, int m2, int j3, int m3) {
    if (m3 != m1 + m2) return 0.0;
    int vmin = -j1 + j2 + m3; if (-j1 + m1 > vmin) vmin = -j1 + m1; if (0 > vmin) vmin = 0;
    int vmax = j2 + j3 + m1; if (j3 - j1 + j2 < vmax) vmax = j3 - j1 + j2; if (j3 + m3 < vmax) vmax = j3 + m3;
    double pref = sqrt((double)(2*j3+1) * dfact(j3+j1-j2) * dfact(j3-j1+j2) * dfact(j1+j2-j3)
                       / dfact(j1+j2+j3+1)
                       * dfact(j3+m3) * dfact(j3-m3)
                       / (dfact(j1-m1) * dfact(j1+m1) * dfact(j2-m2) * dfact(j2+m2)));
    double s = 0.0;
    for (int v = vmin; v <= vmax; ++v) {
        double sign = ((v + j2 + m2) & 1) ? -1.0 : 1.0;
        s += sign / dfact(v) * dfact(j2+j3+m1-v) * dfact(j1-m1+v)
             / (dfact(j3-j1+j2-v) * dfact(j3+m3-v) * dfact(v+j1-j2-m3));
    }
    return pref * s;
}

__device__ void qmat(int l, C2 Q[5][5]) {
    for (int a = 0; a < 5; ++a) for (int b = 0; b < 5; ++b) Q[a][b] = {0.0, 0.0};
    const double is2 = 0.7071067811865475244;
    for (int m = -l; m < 0; ++m) {
        Q[l+m][l-m] = { is2, 0.0 };
        Q[l+m][l+m] = { 0.0, -is2 };
    }
    Q[l][l] = { 1.0, 0.0 };
    for (int m = 1; m <= l; ++m) {
        double s = (m & 1) ? -1.0 : 1.0;
        Q[l+m][l+m] = { s * is2, 0.0 };
        Q[l+m][l-m] = { 0.0, s * is2 };
    }
    C2 f = (l == 0) ? C2{1.0, 0.0} : (l == 1) ? C2{0.0, -1.0} : C2{-1.0, 0.0};
    for (int a = 0; a < 2*l+1; ++a) for (int b = 0; b < 2*l+1; ++b) Q[a][b] = cmul(Q[a][b], f);
}

__global__ void w3j_init_kernel() {
    __shared__ double cgs[125];
    __shared__ double crs[125];
    __shared__ double red[128];

    const int tid = threadIdx.x;
    const int blk = blockIdx.x;
    const int l1 = (blk == 0) ? 2 : 1;
    const int l2 = (blk == 2) ? 1 : 2;
    const int lo = blk == 0 ? 0 : (blk == 1 ? 1 : 2);
    const double alpha = (blk == 0) ? 1.0 : (blk == 1 ? 1.7320508075688772935 : 2.2360679774997896964);
    const int off = (blk == 0) ? 0 : (blk == 1 ? 25 : 70);
    const int d1 = 2*l1+1, d2 = 2*l2+1, d3 = 2*lo+1;
    const int nel = d1 * d2 * d3;

    if (tid < nel) {
        int i = tid / (d2 * d3), k = (tid / d3) % d2, n = tid % d3;
        cgs[tid] = su2cg(l1, i - l1, l2, k - l2, lo, n - lo);
    }
    __syncthreads();

    double cr = 0.0;
    if (tid < nel) {
        C2 Q1[5][5], Q2[5][5], Q3[5][5];
        qmat(l1, Q1); qmat(l2, Q2); qmat(lo, Q3);
        int a = tid / (d2 * d3), b = (tid / d3) % d2, c = tid % d3;
        C2 s = {0.0, 0.0};
        for (int i = 0; i < d1; ++i)
            for (int k = 0; k < d2; ++k) {
                C2 q12 = cmul(Q1[i][a], Q2[k][b]);
                for (int n = 0; n < d3; ++n) {
                    double cg = cgs[(i * d2 + k) * d3 + n];
                    if (cg == 0.0) continue;
                    C2 q3c = { Q3[n][c].r, -Q3[n][c].i };
                    C2 t = cmul(q12, q3c);
                    s.r += t.r * cg; s.i += t.i * cg;
                }
            }
        cr = s.r;
        crs[tid] = cr;
    }

    red[tid] = (tid < nel) ? cr * cr : 0.0;
    __syncthreads();
    for (int stride = 64; stride > 0; stride >>= 1) {
        if (tid < stride) red[tid] += red[tid + stride];
        __syncthreads();
    }
    double inv = alpha * rsqrt(red[0]);

    if (tid < nel) g_w3j[off + tid] = (float)(crs[tid] * inv);
    if (blk == 2 && tid >= 115 && tid < 128) g_w3j[tid] = 0.0f;
}

// ---------------------------------------------------------------------------
// Weight prep
// ---------------------------------------------------------------------------
__global__ void wsplit_kernel(const float* __restrict__ Wl,
                              const float* __restrict__ Wr,
                              const float* __restrict__ Wf) {
    int b = blockIdx.x;
    int which = b / 3, ll = b % 3;
    const float* W = (which == 0 ? Wl : which == 1 ? Wr : Wf) + ll * CDIM * CDIM;
    char* img = g_wimg + (size_t)b * WIMG_B;
    for (int i = threadIdx.x; i < CDIM * CDIM; i += blockDim.x) {
        int cout = i >> 7, k = i & 127;
        *(__half*)(img + (cout * PITCH + k) * 2) = __float2half_rn(W[i]);
    }
}

// ---------------------------------------------------------------------------
// LR GEMM: fp32 in, 2 fp16 outputs, m = 1..8 only. 2 CTAs/SM.
// Warp-per-output layout: o = wid>>2, 4 warps/output; each warp 32 rows x
// 32 couts of ONE output with its W frags fully register-cached (64 regs).
// Mainloop LDSM = A only.
// ---------------------------------------------------------------------------
__global__ __launch_bounds__(256, 2)
void lr_gemm_kernel(const float* __restrict__ src,
                    __half* __restrict__ out0,
                    __half* __restrict__ out1)
{
    extern __shared__ __align__(16) char smem[];
    char* Wsm   = smem;
    char* A_img = smem + 2 * WIMG_B;
    char* stg   = A_img + AIMG_B;

    const int tid = threadIdx.x, wid = tid >> 5, lane = tid & 31;
    const int g = lane >> 2, t = lane & 3;
    const int m = blockIdx.y + 1;                  // m = 1..8
    const int l = (m >= 4) ? 2 : 1;
    const int o = wid >> 2;                        // output (0=left, 1=right)
    const int warpC = wid & 3;                     // 32-cout group

    // Stage W images once (left = wb 0+l, right = wb 3+l)
    {
        const float4* s0 = (const float4*)(g_wimg + (size_t)l * WIMG_B);
        const float4* s1 = (const float4*)(g_wimg + (size_t)(3 + l) * WIMG_B);
        float4* d0 = (float4*)Wsm;
        float4* d1 = (float4*)(Wsm + WIMG_B);
        for (int i = tid; i < WIMG_B / 16; i += 256) { d0[i] = s0[i]; d1[i] = s1[i]; }
    }

    const int jm = lane >> 3, rr = lane & 7;
    uint32_t aoff[2];
    #pragma unroll
    for (int mf = 0; mf < 2; ++mf) {
        int row = mf * 16 + ((jm & 1) << 3) + rr;
        aoff[mf] = (uint32_t)((row * PITCH + ((jm >> 1) << 3)) * 2);
    }
    uint32_t boff[2];
    #pragma unroll
    for (int cp = 0; cp < 2; ++cp) {
        int n = warpC * 32 + cp * 16 + ((jm >> 1) << 3) + rr;
        boff[cp] = (uint32_t)((n * PITCH + ((jm & 1) << 3)) * 2);
    }

    const uint32_t uA = smem_u32(A_img);
    const uint32_t uWo = smem_u32(Wsm) + (uint32_t)(o * WIMG_B);
    const uint32_t uStg = smem_u32(stg);

    auto issue_chunk = [&](int c) {
        int n0 = c * CHUNK;
        #pragma unroll
        for (int it = 0; it < 4; ++it) {
            int idx = it * 256 + tid;
            int row = idx >> 5, c4 = (idx & 31) << 2;
            int n = n0 + row;
            cp_async16(uStg + (uint32_t)idx * 16,
                       &src[((size_t)n * MDIM + m) * CDIM + c4],
                       n < NNODES);
        }
        cp_commit();
    };

    int c = blockIdx.x;
    if (c < NCHUNKS) issue_chunk(c);

    __syncthreads();   // W staged

    // Cache this warp's W fragments: [ks][cp][4] = 64 regs
    uint32_t B[8][2][4];
    #pragma unroll
    for (int ks = 0; ks < 8; ++ks) {
        const uint32_t kofs = (uint32_t)(ks * 32);
        #pragma unroll
        for (int cp = 0; cp < 2; ++cp)
            ldsm_x4(B[ks][cp][0], B[ks][cp][1], B[ks][cp][2], B[ks][cp][3],
                    uWo + boff[cp] + kofs);
    }

    __half* out = o ? out1 : out0;

    for (; c < NCHUNKS; c += GRP_LR) {
        const int n0 = c * CHUNK;
        cp_wait0();
        __syncthreads();

        #pragma unroll
        for (int it = 0; it < 4; ++it) {
            int idx = it * 256 + tid;
            int row = idx >> 5, c4 = (idx & 31) << 2;
            float4 v = *(float4*)(stg + idx * 16);
            __half2 h01 = __floats2half2_rn(v.x, v.y);
            __half2 h23 = __floats2half2_rn(v.z, v.w);
            *(uint2*)(A_img + (row * PITCH + c4) * 2) =
                make_uint2(*(uint32_t*)&h01, *(uint32_t*)&h23);
        }
        __syncthreads();

        if (c + GRP_LR < NCHUNKS) issue_chunk(c + GRP_LR);

        float acc[2][4][4];
        #pragma unroll
        for (int mf = 0; mf < 2; ++mf)
            #pragma unroll
            for (int cf = 0; cf < 4; ++cf)
                #pragma unroll
                for (int q = 0; q < 4; ++q) acc[mf][cf][q] = 0.f;

        #pragma unroll
        for (int ks = 0; ks < 8; ++ks) {
            const uint32_t kofs = (uint32_t)(ks * 32);
            uint32_t a0[4], a1[4];
            ldsm_x4(a0[0], a0[1], a0[2], a0[3], uA + aoff[0] + kofs);
            ldsm_x4(a1[0], a1[1], a1[2], a1[3], uA + aoff[1] + kofs);
            #pragma unroll
            for (int cp = 0; cp < 2; ++cp) {
                mma_f16(acc[0][2*cp],     a0, B[ks][cp][0], B[ks][cp][1]);
                mma_f16(acc[0][2*cp + 1], a0, B[ks][cp][2], B[ks][cp][3]);
                mma_f16(acc[1][2*cp],     a1, B[ks][cp][0], B[ks][cp][1]);
                mma_f16(acc[1][2*cp + 1], a1, B[ks][cp][2], B[ks][cp][3]);
            }
        }

        #pragma unroll
        for (int mf = 0; mf < 2; ++mf) {
            int r0 = n0 + mf * 16 + g;
            int r1 = r0 + 8;
            #pragma unroll
            for (int cf = 0; cf < 4; ++cf) {
                int cb = warpC * 32 + cf * 8 + 2 * t;
                if (r0 < NNODES) {
                    __half2 h = __floats2half2_rn(acc[mf][cf][0], acc[mf][cf][1]);
                    *(uint32_t*)&out[((size_t)r0 * MDIM + m) * CDIM + cb] = *(uint32_t*)&h;
                }
                if (r1 < NNODES) {
                    __half2 h = __floats2half2_rn(acc[mf][cf][2], acc[mf][cf][3]);
                    *(uint32_t*)&out[((size_t)r1 * MDIM + m) * CDIM + cb] = *(uint32_t*)&h;
                }
            }
        }
    }
}

// ---------------------------------------------------------------------------
// Final GEMM: fp16 in (direct cp.async, double-buffered), fp32 out. 2 CTAs/SM.
// ALL W fragments register-cached; mainloop LDSM = A only.
// ---------------------------------------------------------------------------
__global__ __launch_bounds__(256, 2)
void f_gemm_kernel(const __half* __restrict__ src,
                   const float* __restrict__ bias0,
                   float* __restrict__ out0)
{
    extern __shared__ __align__(16) char smem[];
    char* Wsm  = smem;
    char* Aimg[2] = { smem + WIMG_B, smem + WIMG_B + AIMG_B };

    const int tid = threadIdx.x, wid = tid >> 5, lane = tid & 31;
    const int g = lane >> 2, t = lane & 3;
    const int m = blockIdx.y;
    const int l = (m >= 4) ? 2 : (m >= 1) ? 1 : 0;
    const int warpR = wid & 1, warpC = wid >> 1;

    {
        const float4* s0 = (const float4*)(g_wimg + (size_t)(6 + l) * WIMG_B);
        float4* d0 = (float4*)Wsm;
        for (int i = tid; i < WIMG_B / 16; i += 256) d0[i] = s0[i];
    }

    const int jm = lane >> 3, rr = lane & 7;
    const uint32_t aoff = (uint32_t)(((warpR * 16 + ((jm & 1) << 3) + rr) * PITCH
                                      + ((jm >> 1) << 3)) * 2);
    uint32_t boff[2];
    #pragma unroll
    for (int cp = 0; cp < 2; ++cp) {
        int n = warpC * 32 + cp * 16 + ((jm >> 1) << 3) + rr;
        boff[cp] = (uint32_t)((n * PITCH + ((jm & 1) << 3)) * 2);
    }
    const uint32_t uW = smem_u32(Wsm);
    const uint32_t uAimg[2] = { smem_u32(Aimg[0]), smem_u32(Aimg[1]) };

    auto issue_chunk = [&](int c, int buf) {
        int n0 = c * CHUNK;
        #pragma unroll
        for (int it = 0; it < 2; ++it) {
            int idx = it * 256 + tid;
            int row = idx >> 4, c8 = (idx & 15) << 3;
            int n = n0 + row;
            cp_async16(uAimg[buf] + (uint32_t)(row * PITCH + c8) * 2,
                       &src[((size_t)n * MDIM + m) * CDIM + c8],
                       n < NNODES);
        }
        cp_commit();
    };

    int c = blockIdx.x;
    int buf = 0;
    if (c < NCHUNKS) issue_chunk(c, 0);

    __syncthreads();   // W staged

    uint32_t B[8][2][4];
    #pragma unroll
    for (int ks = 0; ks < 8; ++ks) {
        const uint32_t kofs = (uint32_t)(ks * 32);
        #pragma unroll
        for (int cp = 0; cp < 2; ++cp)
            ldsm_x4(B[ks][cp][0], B[ks][cp][1], B[ks][cp][2], B[ks][cp][3],
                    uW + boff[cp] + kofs);
    }

    for (; c < NCHUNKS; c += GRP_F) {
        const int n0 = c * CHUNK;
        bool more = (c + GRP_F < NCHUNKS);
        if (more) issue_chunk(c + GRP_F, buf ^ 1);
        if (more) cp_wait1(); else cp_wait0();
        __syncthreads();

        const uint32_t uA = uAimg[buf];
        float acc[4][4];
        #pragma unroll
        for (int cf = 0; cf < 4; ++cf)
            #pragma unroll
            for (int q = 0; q < 4; ++q) acc[cf][q] = 0.f;

        #pragma unroll
        for (int ks = 0; ks < 8; ++ks) {
            const uint32_t kofs = (uint32_t)(ks * 32);
            uint32_t a[4];
            ldsm_x4(a[0], a[1], a[2], a[3], uA + aoff + kofs);
            #pragma unroll
            for (int cp = 0; cp < 2; ++cp) {
                mma_f16(acc[2*cp],     a, B[ks][cp][0], B[ks][cp][1]);
                mma_f16(acc[2*cp + 1], a, B[ks][cp][2], B[ks][cp][3]);
            }
        }

        {
            int r0 = n0 + warpR * 16 + g;
            int r1 = r0 + 8;
            #pragma unroll
            for (int cf = 0; cf < 4; ++cf) {
                int cb = warpC * 32 + cf * 8 + 2 * t;
                float bx = 0.f, by = 0.f;
                if (m == 0) { bx = bias0[cb]; by = bias0[cb + 1]; }
                if (r0 < NNODES)
                    *(float2*)&out0[((size_t)r0 * MDIM + m) * CDIM + cb] =
                        make_float2(acc[cf][0] + bx, acc[cf][1] + by);
                if (r1 < NNODES)
                    *(float2*)&out0[((size_t)r1 * MDIM + m) * CDIM + cb] =
                        make_float2(acc[cf][2] + bx, acc[cf][3] + by);
            }
        }
        __syncthreads();
        buf ^= 1;
    }
}

// ---------------------------------------------------------------------------
// Channel-wise CG tensor product, 4 ch/thread, f32x2 packed math (FFMA2).
// Per-lane arithmetic identical to scalar FFMA (same IEEE rounding).
// ---------------------------------------------------------------------------
__global__ __launch_bounds__(256)
void tp_kernel() {
    __shared__ ull w3p[128];     // packed (w, w)
    if (threadIdx.x < 128) {
        float w = g_w3j[threadIdx.x];
        w3p[threadIdx.x] = pack2(w, w);
    }
    __syncthreads();

    int p = blockIdx.x * 256 + threadIdx.x;
    if (p >= NNODES * (CDIM / 4)) return;
    int node = p >> 5, q = p & 31;
    const uint2* XL = (const uint2*)g_xl;
    const uint2* XR = (const uint2*)g_xr;
    uint2* OUT = (uint2*)g_xl;
    size_t base = (size_t)node * (MDIM * 32) + q;

    // load + unpack to packed f32x2 (2 ull per quantity = 4 channels)
    ull a1[3][2], b1[3][2], a2[5][2], b2[5][2];
    #pragma unroll
    for (int i = 0; i < 3; ++i) {
        uint2 va = XL[base + (1 + i) * 32];
        uint2 vb = XR[base + (1 + i) * 32];
        float2 f;
        f = __half22float2(*(__half2*)&va.x); a1[i][0] = pack2(f.x, f.y);
        f = __half22float2(*(__half2*)&va.y); a1[i][1] = pack2(f.x, f.y);
        f = __half22float2(*(__half2*)&vb.x); b1[i][0] = pack2(f.x, f.y);
        f = __half22float2(*(__half2*)&vb.y); b1[i][1] = pack2(f.x, f.y);
    }
    #pragma unroll
    for (int i = 0; i < 5; ++i) {
        uint2 va = XL[base + (4 + i) * 32];
        uint2 vb = XR[base + (4 + i) * 32];
        float2 f;
        f = __half22float2(*(__half2*)&va.x); a2[i][0] = pack2(f.x, f.y);
        f = __half22float2(*(__half2*)&va.y); a2[i][1] = pack2(f.x, f.y);
        f = __half22float2(*(__half2*)&vb.x); b2[i][0] = pack2(f.x, f.y);
        f = __half22float2(*(__half2*)&vb.y); b2[i][1] = pack2(f.x, f.y);
    }

    const ull Z = pack2(0.f, 0.f);
    ull o0[2] = { Z, Z };
    ull o1[3][2] = { {Z,Z}, {Z,Z}, {Z,Z} };
    ull o2[5][2] = { {Z,Z}, {Z,Z}, {Z,Z}, {Z,Z}, {Z,Z} };

    // (2,2,0)
    #pragma unroll
    for (int i = 0; i < 5; ++i)
        #pragma unroll
        for (int j = 0; j < 5; ++j) {
            ull w = w3p[i * 5 + j];
            #pragma unroll
            for (int h = 0; h < 2; ++h) {
                ull ab = mul2(a2[i][h], b2[j][h]);
                ffma2(o0[h], w, ab);
            }
        }

    // (1,2,1)
    #pragma unroll
    for (int i = 0; i < 3; ++i)
        #pragma unroll
        for (int j = 0; j < 5; ++j) {
            ull ab[2];
            #pragma unroll
            for (int h = 0; h < 2; ++h) ab[h] = mul2(a1[i][h], b2[j][h]);
            #pragma unroll
            for (int k = 0; k < 3; ++k) {
                ull w = w3p[25 + (i * 5 + j) * 3 + k];
                ffma2(o1[k][0], w, ab[0]);
                ffma2(o1[k][1], w, ab[1]);
            }
        }

    // (1,1,2)
    #pragma unroll
    for (int i = 0; i < 3; ++i)
        #pragma unroll
        for (int j = 0; j < 3; ++j) {
            ull ab[2];
            #pragma unroll
            for (int h = 0; h < 2; ++h) ab[h] = mul2(a1[i][h], b1[j][h]);
            #pragma unroll
            for (int k = 0; k < 5; ++k) {
                ull w = w3p[70 + (i * 3 + j) * 5 + k];
                ffma2(o2[k][0], w, ab[0]);
                ffma2(o2[k][1], w, ab[1]);
            }
        }

    auto pk = [](ull lo, ull hi) {
        float lx, ly, hx, hy;
        unpack2(lo, lx, ly); unpack2(hi, hx, hy);
        __half2 hlo = __floats2half2_rn(lx, ly);
        __half2 hhi = __floats2half2_rn(hx, hy);
        return make_uint2(*(uint32_t*)&hlo, *(uint32_t*)&hhi);
    };

    OUT[base] = pk(o0[0], o0[1]);
    #pragma unroll
    for (int k = 0; k < 3; ++k) OUT[base + (1 + k) * 32] = pk(o1[k][0], o1[k][1]);
    #pragma unroll
    for (int k = 0; k < 5; ++k) OUT[base + (4 + k) * 32] = pk(o2[k][0], o2[k][1]);
}

// ---------------------------------------------------------------------------
extern "C" void kernel_launch(void* const* d_in, const int* in_sizes, int n_in,
                              void* d_out, int out_size) {
    const float* x  = (const float*)d_in[0];
    const float* Wl = (const float*)d_in[1];
    const float* Wr = (const float*)d_in[3];
    const float* Wf = (const float*)d_in[5];
    const float* bf = (const float*)d_in[6];
    float* out = (float*)d_out;

    __half *pxl = nullptr, *pxr = nullptr;
    cudaGetSymbolAddress((void**)&pxl, g_xl);
    cudaGetSymbolAddress((void**)&pxr, g_xr);

    const int LR_SMEM = 2 * WIMG_B + AIMG_B + STG_B;   // 94720  -> 2 CTAs/SM
    const int F_SMEM  = WIMG_B + 2 * AIMG_B;           // 52224
    cudaFuncSetAttribute(lr_gemm_kernel,
                         cudaFuncAttributeMaxDynamicSharedMemorySize, LR_SMEM);
    cudaFuncSetAttribute(f_gemm_kernel,
                         cudaFuncAttributeMaxDynamicSharedMemorySize, F_SMEM);

    w3j_init_kernel<<<3, 128>>>();
    wsplit_kernel<<<9, 256>>>(Wl, Wr, Wf);

    // left + right linears, m=1..8 only
    lr_gemm_kernel<<<dim3(GRP_LR, 8), 256, LR_SMEM>>>(x, pxl, pxr);
    // CG tensor product (fp16 in/out, 4 ch/thread, FFMA2)
    tp_kernel<<<(NNODES * (CDIM / 4) + 255) / 256, 256>>>();
    // final linear (fp16 input) -> fp32 d_out
    f_gemm_kernel<<<dim3(GRP_F, MDIM), 256, F_SMEM>>>(pxl, bf, out);
}